// round 6
// baseline (speedup 1.0000x reference)
#include <cuda_runtime.h>
#include <cuda_bf16.h>
#include <math.h>
#include <stdint.h>

// Problem constants
#define DD 256
#define SS 128
#define QQ 64
#define PP 64
#define M_ROWS 8192   // S*Q
#define N_COLS 8192   // S*P

// K2 tiling
#define BM 128                 // rows per block (2 sections)
#define NT 128                 // cols per B tile
#define CSPLIT 4               // column splits
#define CCOLS (N_COLS/CSPLIT)  // 2048
#define LDT 264                // padded smem row stride (bf16 elems)

static __device__ __align__(16) __nv_bfloat16 g_qn[M_ROWS * DD];     // 4 MB
static __device__ __align__(16) __nv_bfloat16 g_sn[N_COLS * DD];     // 4 MB
static __device__ __align__(16) float         g_stn[SS * DD];        // 128 KB
static __device__ __align__(16) float         g_pos[M_ROWS * PP];    // 2 MB
static __device__ __align__(16) float         g_total[CSPLIT * M_ROWS];
static __device__                double        g_qs_part[128];
static __device__ __align__(16) float         g_sq_den_part[128 * 128];

// ---------------------------------------------------------------------------
// K1: L2-normalize rows. One warp per row.
//   rows [0,8192)       : questions  -> g_qn (bf16)
//   rows [8192,16384)   : sentences  -> g_sn (bf16)
//   rows [16384,16512)  : section titles -> g_stn (f32)
// ---------------------------------------------------------------------------
__global__ void __launch_bounds__(256) k1_normalize(const float* __restrict__ sec,
                                                    const float* __restrict__ ques,
                                                    const float* __restrict__ sent) {
    int wid = (blockIdx.x * blockDim.x + threadIdx.x) >> 5;
    int l = threadIdx.x & 31;
    if (wid >= 16512) return;

    const float* src;
    if (wid < 8192)        src = ques + (size_t)wid * DD;
    else if (wid < 16384)  src = sent + (size_t)(wid - 8192) * DD;
    else                   src = sec  + (size_t)(wid - 16384) * DD;

    float x[8];
    float ss = 0.f;
#pragma unroll
    for (int j = 0; j < 8; j++) { x[j] = src[j * 32 + l]; ss = fmaf(x[j], x[j], ss); }
#pragma unroll
    for (int o = 16; o; o >>= 1) ss += __shfl_xor_sync(0xffffffffu, ss, o);
    float scale = 1.0f / fmaxf(sqrtf(ss), 1e-12f);

    if (wid < 8192) {
        __nv_bfloat16* dst = g_qn + (size_t)wid * DD;
#pragma unroll
        for (int j = 0; j < 8; j++) dst[j * 32 + l] = __float2bfloat16(x[j] * scale);
    } else if (wid < 16384) {
        __nv_bfloat16* dst = g_sn + (size_t)(wid - 8192) * DD;
#pragma unroll
        for (int j = 0; j < 8; j++) dst[j * 32 + l] = __float2bfloat16(x[j] * scale);
    } else {
        float* dst = g_stn + (size_t)(wid - 16384) * DD;
#pragma unroll
        for (int j = 0; j < 8; j++) dst[j * 32 + l] = x[j] * scale;
    }
}

// ---------------------------------------------------------------------------
// K2: big pass.  C[128 rows x 2048 cols] = qn_tile @ sn^T (k=256) via
// mma.sync m16n8k16 bf16; fused exp(./T) row-sums + diag pos store.
// grid = (64 row-blocks, 4 col-splits), 256 threads (8 warps, 4x2 layout).
// ---------------------------------------------------------------------------
__device__ __forceinline__ void mma16816(float* c, const uint32_t* a, const uint32_t* b) {
    asm volatile(
        "mma.sync.aligned.m16n8k16.row.col.f32.bf16.bf16.f32 "
        "{%0,%1,%2,%3}, {%4,%5,%6,%7}, {%8,%9}, {%0,%1,%2,%3};\n"
        : "+f"(c[0]), "+f"(c[1]), "+f"(c[2]), "+f"(c[3])
        : "r"(a[0]), "r"(a[1]), "r"(a[2]), "r"(a[3]), "r"(b[0]), "r"(b[1]));
}

__global__ void __launch_bounds__(256, 1) k2_qs_gemm() {
    extern __shared__ __align__(16) char smem_raw[];
    __nv_bfloat16* sA = reinterpret_cast<__nv_bfloat16*>(smem_raw);           // [BM][LDT]
    __nv_bfloat16* sB = sA + BM * LDT;                                        // [NT][LDT]

    const int tid = threadIdx.x;
    const int wid = tid >> 5;
    const int lane = tid & 31;
    const int qg = lane >> 2;   // groupID
    const int qt = lane & 3;    // thread-in-group

    const int rowBlk = blockIdx.x;          // 0..63
    const int split  = blockIdx.y;          // 0..3
    const int row0   = rowBlk * BM;
    const int col0   = split * CCOLS;

    const int warp_m = (wid & 3) * 32;      // 0,32,64,96
    const int warp_n = (wid >> 2) * 64;     // 0,64

    // Load A tile (128 rows x 256 bf16)
    {
        const uint4* srcA = reinterpret_cast<const uint4*>(g_qn) + (size_t)row0 * (DD / 8);
#pragma unroll
        for (int i = tid; i < BM * (DD / 8); i += 256) {
            int r = i >> 5, c = i & 31;
            *reinterpret_cast<uint4*>(sA + r * LDT + c * 8) = srcA[i];
        }
    }

    const float invT = 1.0f / 0.07f;
    float rsum[4] = {0.f, 0.f, 0.f, 0.f};

    for (int it = 0; it < CCOLS / NT; ++it) {
        const int cb = col0 + it * NT;
        if (it > 0) __syncthreads();     // previous sB fully consumed
        // Load B tile (128 rows x 256 bf16)
        {
            const uint4* srcB = reinterpret_cast<const uint4*>(g_sn) + (size_t)cb * (DD / 8);
#pragma unroll
            for (int i = tid; i < NT * (DD / 8); i += 256) {
                int r = i >> 5, c = i & 31;
                *reinterpret_cast<uint4*>(sB + r * LDT + c * 8) = srcB[i];
            }
        }
        __syncthreads();

        float acc[2][8][4];
#pragma unroll
        for (int mt = 0; mt < 2; mt++)
#pragma unroll
            for (int nt = 0; nt < 8; nt++)
#pragma unroll
                for (int j = 0; j < 4; j++) acc[mt][nt][j] = 0.f;

#pragma unroll
        for (int ks = 0; ks < 16; ++ks) {
            const int kb = ks * 16;
            uint32_t a[2][4], b[8][2];
#pragma unroll
            for (int mt = 0; mt < 2; mt++) {
                const __nv_bfloat16* base = sA + (warp_m + mt * 16 + qg) * LDT + kb + qt * 2;
                a[mt][0] = *reinterpret_cast<const uint32_t*>(base);
                a[mt][1] = *reinterpret_cast<const uint32_t*>(base + 8 * LDT);
                a[mt][2] = *reinterpret_cast<const uint32_t*>(base + 8);
                a[mt][3] = *reinterpret_cast<const uint32_t*>(base + 8 * LDT + 8);
            }
#pragma unroll
            for (int nt = 0; nt < 8; nt++) {
                const __nv_bfloat16* base = sB + (warp_n + nt * 8 + qg) * LDT + kb + qt * 2;
                b[nt][0] = *reinterpret_cast<const uint32_t*>(base);
                b[nt][1] = *reinterpret_cast<const uint32_t*>(base + 8);
            }
#pragma unroll
            for (int mt = 0; mt < 2; mt++)
#pragma unroll
                for (int nt = 0; nt < 8; nt++)
                    mma16816(acc[mt][nt], a[mt], b[nt]);
        }

        // Epilogue: exp + row sums (+ diag pos store on the owning tile)
        const bool diag = (cb == row0);  // diag cols for both sections == [row0, row0+128)
#pragma unroll
        for (int mt = 0; mt < 2; mt++) {
#pragma unroll
            for (int h = 0; h < 2; h++) {
                float rs = 0.f;
#pragma unroll
                for (int nt = 0; nt < 8; nt++) {
                    float e0 = __expf(acc[mt][nt][h * 2 + 0] * invT);
                    float e1 = __expf(acc[mt][nt][h * 2 + 1] * invT);
                    rs += e0 + e1;
                    if (diag) {
                        int rloc = warp_m + mt * 16 + h * 8 + qg;
                        int col  = cb + warp_n + nt * 8 + qt * 2;
                        int grow = row0 + rloc;
                        if ((col >> 6) == (grow >> 6)) {   // same section
                            g_pos[(size_t)grow * PP + (col & 63)]       = e0;
                            g_pos[(size_t)grow * PP + ((col + 1) & 63)] = e1;
                        }
                    }
                }
                rsum[mt * 2 + h] += rs;
            }
        }
    }

    // Row-sum reduction: quad (t) shuffle, then across the 2 warp-column groups.
    __syncthreads();
    float* rsm = reinterpret_cast<float*>(smem_raw);   // reuse smem: [128 rows][2]
#pragma unroll
    for (int k = 0; k < 4; ++k) {
        float v = rsum[k];
        v += __shfl_xor_sync(0xffffffffu, v, 1);
        v += __shfl_xor_sync(0xffffffffu, v, 2);
        if (qt == 0) {
            int mt = k >> 1, h = k & 1;
            int rloc = warp_m + mt * 16 + h * 8 + qg;
            rsm[rloc * 2 + (wid >> 2)] = v;
        }
    }
    __syncthreads();
    if (tid < BM) {
        g_total[split * M_ROWS + row0 + tid] = rsm[tid * 2] + rsm[tid * 2 + 1];
    }
}

// ---------------------------------------------------------------------------
// K3: qs loss.  One warp handles 8 rows; per row: own = sum_p pos, neg = total-own,
// term = -log(pos/(pos+N_g)).  Double accumulation, deterministic.
// grid = 128 blocks x 256 threads -> g_qs_part[128].
// ---------------------------------------------------------------------------
__global__ void __launch_bounds__(256) k3_qs_loss() {
    __shared__ double wsum[8];
    const int l = threadIdx.x & 31;
    const int wid = threadIdx.x >> 5;
    const int warpGlobal = blockIdx.x * 8 + wid;

    const float invL = 1.0f / 0.9f;                       // 1/(1-LAM)
    const float term2 = expf(-1.0f / 0.07f) * 8191.0f;    // exp(-1/T)*(N_e-1)

    double acc = 0.0;
    for (int rr = 0; rr < 8; rr++) {
        int row = warpGlobal * 8 + rr;
        float p0 = g_pos[(size_t)row * PP + l];
        float p1 = g_pos[(size_t)row * PP + 32 + l];
        float own = p0 + p1;
#pragma unroll
        for (int o = 16; o; o >>= 1) own += __shfl_xor_sync(0xffffffffu, own, o);
        float total = g_total[row] + g_total[M_ROWS + row] +
                      g_total[2 * M_ROWS + row] + g_total[3 * M_ROWS + row];
        float c1 = (total - own) * invL;

        float t1 = fmaf(-0.1f, p0, c1);
        float Ng0 = fmaxf(fmaxf(t1, term2), 1e-8f);
        float t2 = fmaf(-0.1f, p1, c1);
        float Ng1 = fmaxf(fmaxf(t2, term2), 1e-8f);
        acc += (double)log1pf(Ng0 / p0) + (double)log1pf(Ng1 / p1);
    }
#pragma unroll
    for (int o = 16; o; o >>= 1) acc += __shfl_xor_sync(0xffffffffu, acc, o);
    if (l == 0) wsum[wid] = acc;
    __syncthreads();
    if (threadIdx.x == 0) {
        double s = 0.0;
        for (int i = 0; i < 8; i++) s += wsum[i];
        g_qs_part[blockIdx.x] = s;
    }
}

// ---------------------------------------------------------------------------
// K4: sq denominator partials.  Block b covers qn rows [b*64,(b+1)*64).
// den_part[b][s] = sum_{r in block} exp(stn[s].qn[r]/T).  num[s] = den_part[s][s].
// 128 blocks x 256 threads; stn + qn rows staged in smem.
// ---------------------------------------------------------------------------
#define K4_SMEM (128 * 256 * 4 + 64 * 257 * 4)
__global__ void __launch_bounds__(256, 1) k4_sq_den() {
    extern __shared__ __align__(16) float smf[];
    float* sS = smf;                 // [128][256] stn (f32)
    float* sQ = smf + 128 * 256;     // [64][257] qn rows (f32, padded)

    const int tid = threadIdx.x;
    const int b = blockIdx.x;
    const int row0 = b * 64;

    for (int i = tid; i < 128 * 256 / 4; i += 256)
        reinterpret_cast<float4*>(sS)[i] = reinterpret_cast<const float4*>(g_stn)[i];
    for (int i = tid; i < 64 * 256; i += 256) {
        int r = i >> 8, d = i & 255;
        sQ[r * 257 + d] = __bfloat162float(g_qn[(size_t)(row0 + r) * DD + d]);
    }
    __syncthreads();

    const int l = tid & 31;
    const int w = tid >> 5;           // s-group: [w*16, w*16+16)
    const int r0 = l * 2;             // two rows per lane

    float acc0[16], acc1[16];
#pragma unroll
    for (int i = 0; i < 16; i++) { acc0[i] = 0.f; acc1[i] = 0.f; }

    const float* q0p = sQ + r0 * 257;
    const float* q1p = sQ + (r0 + 1) * 257;
    const float* sp = sS + w * 16 * 256;

    for (int d = 0; d < 256; d++) {
        float q0 = q0p[d], q1 = q1p[d];
#pragma unroll
        for (int i = 0; i < 16; i++) {
            float sv = sp[i * 256 + d];
            acc0[i] = fmaf(q0, sv, acc0[i]);
            acc1[i] = fmaf(q1, sv, acc1[i]);
        }
    }

    const float invT = 1.0f / 0.07f;
#pragma unroll
    for (int i = 0; i < 16; i++) {
        float v = __expf(acc0[i] * invT) + __expf(acc1[i] * invT);
#pragma unroll
        for (int o = 16; o; o >>= 1) v += __shfl_xor_sync(0xffffffffu, v, o);
        if (l == 0) g_sq_den_part[b * 128 + w * 16 + i] = v;
    }
}

// ---------------------------------------------------------------------------
// K5: final scalar.  sq_loss = sum_s [log(den_s) - log(num_s)]; + sum qs parts.
// at_loss = -log(x/x) = 0.  Single block, deterministic.
// ---------------------------------------------------------------------------
__global__ void __launch_bounds__(128) k5_final(float* __restrict__ out, int out_size) {
    __shared__ double sterm[128];
    __shared__ double sqs[128];
    const int t = threadIdx.x;

    float den = 0.f;
    for (int b = 0; b < 128; b++) den += g_sq_den_part[b * 128 + t];
    float num = g_sq_den_part[t * 128 + t];
    sterm[t] = log((double)den) - log((double)num);
    sqs[t] = g_qs_part[t];
    __syncthreads();

    if (t == 0) {
        double s = 0.0;
        for (int i = 0; i < 128; i++) s += sqs[i];
        for (int i = 0; i < 128; i++) s += sterm[i];
        float v = (float)s;
        for (int i = 0; i < out_size; i++) out[i] = v;
    }
}

// ---------------------------------------------------------------------------
extern "C" void kernel_launch(void* const* d_in, const int* in_sizes, int n_in,
                              void* d_out, int out_size) {
    (void)in_sizes; (void)n_in;
    const float* sec  = (const float*)d_in[1];
    const float* ques = (const float*)d_in[2];
    const float* sent = (const float*)d_in[3];
    float* out = (float*)d_out;

    const int k2_smem = (BM * LDT + NT * LDT) * (int)sizeof(__nv_bfloat16);  // 135168
    cudaFuncSetAttribute(k2_qs_gemm, cudaFuncAttributeMaxDynamicSharedMemorySize, k2_smem);
    cudaFuncSetAttribute(k4_sq_den, cudaFuncAttributeMaxDynamicSharedMemorySize, K4_SMEM);

    k1_normalize<<<2064, 256>>>(sec, ques, sent);
    k2_qs_gemm<<<dim3(64, 4), 256, k2_smem>>>();
    k3_qs_loss<<<128, 256>>>();
    k4_sq_den<<<128, 256, K4_SMEM>>>();
    k5_final<<<1, 128>>>(out, out_size);
}

// round 9
// speedup vs baseline: 1.3931x; 1.3931x over previous
#include <cuda_runtime.h>
#include <cuda_bf16.h>
#include <math.h>
#include <stdint.h>

// Problem constants
#define DD 256
#define SS 128
#define PP 64
#define M_ROWS 8192   // S*Q
#define N_COLS 8192   // S*P

// K2 config: grid (65, 2). Block = 128 rows x 4096 cols, 32 tiles of 128 cols.
#define CSPLIT 2
#define CCOLS (N_COLS / CSPLIT)   // 4096
#define TILE_NB 128               // cols per B tile
#define NTT (CCOLS / TILE_NB)     // 32
#define LDT 264                   // padded smem row stride (bf16 elems)
#define TILE_SZ (128 * LDT * 2)   // 67584 bytes per 128x256 tile
#define SM_A 0
#define SM_B TILE_SZ
#define K2_SMEM (3 * TILE_SZ)     // A + 2 B buffers = 202752

static __device__ __align__(16) __nv_bfloat16 g_qn[M_ROWS * DD];     // 4 MB
static __device__ __align__(16) __nv_bfloat16 g_sn[N_COLS * DD];     // 4 MB
static __device__ __align__(16) __nv_bfloat16 g_stnb[SS * DD];       // 64 KB
static __device__ __align__(16) float         g_pos[M_ROWS * PP];    // 2 MB
static __device__ __align__(16) float         g_total8[CSPLIT * M_ROWS];
static __device__                double        g_qs_part[128];
static __device__ __align__(16) float         g_sqden[CSPLIT * SS];
static __device__ __align__(16) float         g_sqnum[SS];

// ---------------------------------------------------------------------------
// PTX helpers (all legal under virtual arch compute_103 — no 'a' features)
// ---------------------------------------------------------------------------
__device__ __forceinline__ uint32_t smem_u32(const void* p) {
    uint32_t a;
    asm("{ .reg .u64 t; cvta.to.shared.u64 t, %1; cvt.u32.u64 %0, t; }" : "=r"(a) : "l"(p));
    return a;
}
__device__ __forceinline__ void cp_async16(uint32_t dst, const void* src) {
    asm volatile("cp.async.cg.shared.global [%0], [%1], 16;" :: "r"(dst), "l"(src) : "memory");
}
__device__ __forceinline__ void cp_commit() { asm volatile("cp.async.commit_group;" ::: "memory"); }
template <int N> __device__ __forceinline__ void cp_wait() {
    asm volatile("cp.async.wait_group %0;" :: "n"(N) : "memory");
}
__device__ __forceinline__ void ldsm_x4(uint32_t& r0, uint32_t& r1, uint32_t& r2, uint32_t& r3,
                                        uint32_t addr) {
    asm volatile("ldmatrix.sync.aligned.m8n8.x4.shared.b16 {%0,%1,%2,%3}, [%4];"
                 : "=r"(r0), "=r"(r1), "=r"(r2), "=r"(r3) : "r"(addr));
}
__device__ __forceinline__ void mma16816(float* c, const uint32_t* a, const uint32_t* b) {
    asm volatile(
        "mma.sync.aligned.m16n8k16.row.col.f32.bf16.bf16.f32 "
        "{%0,%1,%2,%3}, {%4,%5,%6,%7}, {%8,%9}, {%0,%1,%2,%3};\n"
        : "+f"(c[0]), "+f"(c[1]), "+f"(c[2]), "+f"(c[3])
        : "r"(a[0]), "r"(a[1]), "r"(a[2]), "r"(a[3]), "r"(b[0]), "r"(b[1]));
}
// exp(v/0.07) = 2^(v * log2(e)/0.07)
__device__ __forceinline__ float fexp_t(float v) {
    float r;
    asm("ex2.approx.f32 %0, %1;" : "=f"(r) : "f"(v * 20.60992915555662f));
    return r;
}

// ---------------------------------------------------------------------------
// K1: L2-normalize rows. One warp per row.
//   [0,8192): questions -> g_qn; [8192,16384): sentences -> g_sn;
//   [16384,16512): section titles -> g_stnb. All bf16.
// ---------------------------------------------------------------------------
__global__ void __launch_bounds__(256) k1_normalize(const float* __restrict__ sec,
                                                    const float* __restrict__ ques,
                                                    const float* __restrict__ sent) {
    int wid = (blockIdx.x * blockDim.x + threadIdx.x) >> 5;
    int l = threadIdx.x & 31;
    if (wid >= 16512) return;

    const float* src;
    if (wid < 8192)        src = ques + (size_t)wid * DD;
    else if (wid < 16384)  src = sent + (size_t)(wid - 8192) * DD;
    else                   src = sec  + (size_t)(wid - 16384) * DD;

    float x[8];
    float ss = 0.f;
#pragma unroll
    for (int j = 0; j < 8; j++) { x[j] = src[j * 32 + l]; ss = fmaf(x[j], x[j], ss); }
#pragma unroll
    for (int o = 16; o; o >>= 1) ss += __shfl_xor_sync(0xffffffffu, ss, o);
    float scale = 1.0f / fmaxf(sqrtf(ss), 1e-12f);

    __nv_bfloat16* dst;
    if (wid < 8192)       dst = g_qn   + (size_t)wid * DD;
    else if (wid < 16384) dst = g_sn   + (size_t)(wid - 8192) * DD;
    else                  dst = g_stnb + (size_t)(wid - 16384) * DD;
#pragma unroll
    for (int j = 0; j < 8; j++) dst[j * 32 + l] = __float2bfloat16(x[j] * scale);
}

// ---------------------------------------------------------------------------
// K2: fused big pass (qs + sq GEMMs), mma.sync bf16 + ldmatrix + cp.async.
//  blockIdx.x in [0,64): A = qn rowblock, B = sn  (qs path)
//  blockIdx.x == 64    : A = stn,         B = qn  (sq path)
//  blockIdx.y = column split. 256 threads = 8 warps (4 M x 2 N).
// ---------------------------------------------------------------------------
__global__ void __launch_bounds__(256, 1) k2_fused() {
    extern __shared__ __align__(1024) char smem[];
    const uint32_t smem_base = smem_u32(smem);

    const int tid = threadIdx.x;
    const int wid = tid >> 5;
    const int lane = tid & 31;
    const int qg = lane >> 2;     // group
    const int qt = lane & 3;      // thread-in-group

    const bool modeQ = (blockIdx.x == 64);
    const int row0 = modeQ ? 0 : blockIdx.x * 128;
    const int split = blockIdx.y;
    const int col0 = split * CCOLS;

    const __nv_bfloat16* Asrc = modeQ ? g_stnb : (g_qn + (size_t)row0 * DD);
    const __nv_bfloat16* Bsrc = modeQ ? g_qn : g_sn;

    const int warp_m = (wid & 3) * 32;   // 0,32,64,96
    const int warp_n = (wid >> 2) * 64;  // 0,64

    // ldmatrix address bases (per-thread invariant part)
    const int mat = lane >> 3;           // which 8x8 matrix this lane addresses
    const int mrow = (mat & 1) * 8 + (lane & 7);
    const int mkof = (mat >> 1) * 8;     // k offset 0 or 8
    const uint32_t aBase = smem_base + SM_A +
        (uint32_t)(((warp_m + mrow) * LDT + mkof) * 2);
    const uint32_t bBase0 = smem_base + SM_B +
        (uint32_t)(((warp_n + mrow) * LDT + mkof) * 2);

    // ---- Prefetch B tile 0 into buffer 0 (cp.async) ----
    {
        const __nv_bfloat16* bs = Bsrc + (size_t)col0 * DD;
        const uint32_t dst = smem_base + SM_B;
#pragma unroll
        for (int j = 0; j < 16; ++j) {
            int idx = j * 256 + tid;              // 4096 16B chunks
            int r = idx >> 5, c = idx & 31;
            cp_async16(dst + (uint32_t)((r * LDT + c * 8) * 2), bs + (size_t)r * DD + c * 8);
        }
        cp_commit();
    }

    // ---- Load A tile (128 x 256 bf16) with regular vector loads ----
    {
        const uint4* srcA = reinterpret_cast<const uint4*>(Asrc);
#pragma unroll
        for (int i = tid; i < 128 * 32; i += 256) {
            int r = i >> 5, c = i & 31;
            *reinterpret_cast<uint4*>(smem + SM_A + (r * LDT + c * 8) * 2) = srcA[i];
        }
    }

    const int sec64 = ((row0 + warp_m) >> 6) << 6;   // qs: this warp's pos col-block
    float rsum[4] = {0.f, 0.f, 0.f, 0.f};
    float nsum[4] = {0.f, 0.f, 0.f, 0.f};

    for (int t = 0; t < NTT; ++t) {
        // Prefetch next tile into the other buffer
        if (t + 1 < NTT) {
            const __nv_bfloat16* bs = Bsrc + (size_t)(col0 + (t + 1) * TILE_NB) * DD;
            const uint32_t dst = smem_base + SM_B + ((t + 1) & 1) * TILE_SZ;
#pragma unroll
            for (int j = 0; j < 16; ++j) {
                int idx = j * 256 + tid;
                int r = idx >> 5, c = idx & 31;
                cp_async16(dst + (uint32_t)((r * LDT + c * 8) * 2), bs + (size_t)r * DD + c * 8);
            }
            cp_commit();
            cp_wait<1>();   // current tile's group done
        } else {
            cp_wait<0>();
        }
        __syncthreads();    // buf[t&1] visible to all warps

        const uint32_t bBase = bBase0 + (t & 1) * TILE_SZ;

        float acc[2][8][4];
#pragma unroll
        for (int mt = 0; mt < 2; mt++)
#pragma unroll
            for (int nt = 0; nt < 8; nt++)
#pragma unroll
                for (int j = 0; j < 4; j++) acc[mt][nt][j] = 0.f;

#pragma unroll
        for (int ks = 0; ks < 16; ++ks) {
            const uint32_t kb2 = ks * 32;   // 16 bf16 = 32 bytes per kstep
            uint32_t a[2][4], b[8][2];
            ldsm_x4(a[0][0], a[0][1], a[0][2], a[0][3], aBase + kb2);
            ldsm_x4(a[1][0], a[1][1], a[1][2], a[1][3], aBase + 16 * LDT * 2 + kb2);
            ldsm_x4(b[0][0], b[1][0], b[0][1], b[1][1], bBase + kb2);
            ldsm_x4(b[2][0], b[3][0], b[2][1], b[3][1], bBase + 16 * LDT * 2 + kb2);
            ldsm_x4(b[4][0], b[5][0], b[4][1], b[5][1], bBase + 32 * LDT * 2 + kb2);
            ldsm_x4(b[6][0], b[7][0], b[6][1], b[7][1], bBase + 48 * LDT * 2 + kb2);
#pragma unroll
            for (int mt = 0; mt < 2; mt++)
#pragma unroll
                for (int nt = 0; nt < 8; nt++)
                    mma16816(acc[mt][nt], a[mt], b[nt]);
        }
        __syncthreads();    // all warps done reading buf[t&1]; next prefetch may reuse it

        // Epilogue (registers only) — overlaps next tile's cp.async latency.
        const int cbw = col0 + t * TILE_NB + warp_n;   // this warp's 64-col base
        const bool dgQS = !modeQ && (cbw == sec64);
#pragma unroll
        for (int mt = 0; mt < 2; mt++) {
#pragma unroll
            for (int h = 0; h < 2; h++) {
                const int rloc = warp_m + mt * 16 + h * 8 + qg;
                float rs = 0.f;
                if (dgQS) {
                    float* pp = g_pos + (size_t)(row0 + rloc) * PP + qt * 2;
#pragma unroll
                    for (int nt = 0; nt < 8; nt++) {
                        float e0 = fexp_t(acc[mt][nt][h * 2 + 0]);
                        float e1 = fexp_t(acc[mt][nt][h * 2 + 1]);
                        rs += e0 + e1;
                        pp[nt * 8 + 0] = e0;
                        pp[nt * 8 + 1] = e1;
                    }
                } else {
#pragma unroll
                    for (int nt = 0; nt < 8; nt++) {
                        rs += fexp_t(acc[mt][nt][h * 2 + 0]) +
                              fexp_t(acc[mt][nt][h * 2 + 1]);
                    }
                }
                rsum[mt * 2 + h] += rs;
                if (modeQ && (rloc * 64 == cbw)) nsum[mt * 2 + h] += rs;
            }
        }
    }

    // ---- Row-sum reduction: quad shuffle, then across 2 N-warps via smem ----
    __syncthreads();
    float* rsm = reinterpret_cast<float*>(smem);   // reuse sA region: [128][2]
#pragma unroll
    for (int k = 0; k < 4; ++k) {
        float v = rsum[k];
        v += __shfl_xor_sync(0xffffffffu, v, 1);
        v += __shfl_xor_sync(0xffffffffu, v, 2);
        if (qt == 0) {
            int rloc = warp_m + (k >> 1) * 16 + (k & 1) * 8 + qg;
            rsm[rloc * 2 + (wid >> 2)] = v;
        }
    }
    __syncthreads();
    if (tid < 128) {
        float tot = rsm[tid * 2] + rsm[tid * 2 + 1];
        if (!modeQ) g_total8[split * M_ROWS + row0 + tid] = tot;
        else        g_sqden[split * SS + tid] = tot;
    }

    if (modeQ) {
        __syncthreads();
#pragma unroll
        for (int k = 0; k < 4; ++k) {
            float v = nsum[k];
            v += __shfl_xor_sync(0xffffffffu, v, 1);
            v += __shfl_xor_sync(0xffffffffu, v, 2);
            if (qt == 0) {
                int rloc = warp_m + (k >> 1) * 16 + (k & 1) * 8 + qg;
                rsm[rloc * 2 + (wid >> 2)] = v;
            }
        }
        __syncthreads();
        // Section tid's own-question block lives in split (tid >> 6) only.
        if (tid < 128 && (tid >> 6) == split)
            g_sqnum[tid] = rsm[tid * 2] + rsm[tid * 2 + 1];
    }
}

// ---------------------------------------------------------------------------
// K3: qs loss. One warp handles 8 rows; double accumulation, deterministic.
// ---------------------------------------------------------------------------
__global__ void __launch_bounds__(256) k3_qs_loss() {
    __shared__ double wsum[8];
    const int l = threadIdx.x & 31;
    const int wid = threadIdx.x >> 5;
    const int warpGlobal = blockIdx.x * 8 + wid;

    const float invL = 1.0f / 0.9f;                       // 1/(1-LAM)
    const float term2 = expf(-1.0f / 0.07f) * 8191.0f;    // exp(-1/T)*(N_e-1)

    double acc = 0.0;
    for (int rr = 0; rr < 8; rr++) {
        int row = warpGlobal * 8 + rr;
        float p0 = g_pos[(size_t)row * PP + l];
        float p1 = g_pos[(size_t)row * PP + 32 + l];
        float own = p0 + p1;
#pragma unroll
        for (int o = 16; o; o >>= 1) own += __shfl_xor_sync(0xffffffffu, own, o);
        float total = g_total8[row] + g_total8[M_ROWS + row];
        float c1 = (total - own) * invL;

        float t1 = fmaf(-0.1f, p0, c1);
        float Ng0 = fmaxf(fmaxf(t1, term2), 1e-8f);
        float t2 = fmaf(-0.1f, p1, c1);
        float Ng1 = fmaxf(fmaxf(t2, term2), 1e-8f);
        acc += (double)log1pf(Ng0 / p0) + (double)log1pf(Ng1 / p1);
    }
#pragma unroll
    for (int o = 16; o; o >>= 1) acc += __shfl_xor_sync(0xffffffffu, acc, o);
    if (l == 0) wsum[wid] = acc;
    __syncthreads();
    if (threadIdx.x == 0) {
        double s = 0.0;
        for (int i = 0; i < 8; i++) s += wsum[i];
        g_qs_part[blockIdx.x] = s;
    }
}

// ---------------------------------------------------------------------------
// K5: final scalar. sq_loss = sum_s [log(den_s)-log(num_s)]; at_loss = 0.
// ---------------------------------------------------------------------------
__global__ void __launch_bounds__(128) k5_final(float* __restrict__ out, int out_size) {
    __shared__ double sterm[128];
    __shared__ double sqs[128];
    const int t = threadIdx.x;

    float den = g_sqden[t] + g_sqden[SS + t];
    float num = g_sqnum[t];
    sterm[t] = log((double)den) - log((double)num);
    sqs[t] = g_qs_part[t];
    __syncthreads();

    if (t == 0) {
        double s = 0.0;
        for (int i = 0; i < 128; i++) s += sqs[i];
        for (int i = 0; i < 128; i++) s += sterm[i];
        float v = (float)s;
        for (int i = 0; i < out_size; i++) out[i] = v;
    }
}

// ---------------------------------------------------------------------------
extern "C" void kernel_launch(void* const* d_in, const int* in_sizes, int n_in,
                              void* d_out, int out_size) {
    (void)in_sizes; (void)n_in;
    const float* sec  = (const float*)d_in[1];
    const float* ques = (const float*)d_in[2];
    const float* sent = (const float*)d_in[3];
    float* out = (float*)d_out;

    cudaFuncSetAttribute(k2_fused, cudaFuncAttributeMaxDynamicSharedMemorySize, K2_SMEM);

    k1_normalize<<<2064, 256>>>(sec, ques, sent);
    k2_fused<<<dim3(65, CSPLIT), 256, K2_SMEM>>>();
    k3_qs_loss<<<128, 256>>>();
    k5_final<<<1, 128>>>(out, out_size);
}

// round 10
// speedup vs baseline: 1.4856x; 1.0663x over previous
#include <cuda_runtime.h>
#include <cuda_bf16.h>
#include <math.h>
#include <stdint.h>

// Problem constants
#define DD 256
#define SS 128
#define PP 64
#define M_ROWS 8192   // S*Q
#define N_COLS 8192   // S*P

// K2 config: grid (65, 2). Block = 128 rows x 4096 cols, 32 tiles of 128 cols.
#define CSPLIT 2
#define CCOLS (N_COLS / CSPLIT)   // 4096
#define TILE_NB 128               // cols per B tile
#define NTT (CCOLS / TILE_NB)     // 32
#define LDT 264                   // padded smem row stride (bf16 elems)
#define TILE_SZ (128 * LDT * 2)   // 67584 bytes per 128x256 tile
#define SM_A 0
#define SM_B TILE_SZ
#define K2_SMEM (3 * TILE_SZ)     // A + 2 B buffers = 202752

// qn is pre-scaled by log2(e)/TEMP so exp(sim/T) == ex2(acc) directly.
#define QSCALE 20.60992915555662f

static __device__ __align__(16) __nv_bfloat16 g_qn[M_ROWS * DD];     // 4 MB (scaled by QSCALE)
static __device__ __align__(16) __nv_bfloat16 g_sn[N_COLS * DD];     // 4 MB
static __device__ __align__(16) __nv_bfloat16 g_stnb[SS * DD];       // 64 KB
static __device__ __align__(16) float         g_pos[M_ROWS * PP];    // 2 MB
static __device__ __align__(16) float         g_total8[CSPLIT * M_ROWS];
static __device__                double        g_qs_part[128];
static __device__ __align__(16) float         g_sqden[CSPLIT * SS];
static __device__ __align__(16) float         g_sqnum[SS];

// ---------------------------------------------------------------------------
// PTX helpers (all legal under virtual arch compute_103 — no 'a' features)
// ---------------------------------------------------------------------------
__device__ __forceinline__ uint32_t smem_u32(const void* p) {
    uint32_t a;
    asm("{ .reg .u64 t; cvta.to.shared.u64 t, %1; cvt.u32.u64 %0, t; }" : "=r"(a) : "l"(p));
    return a;
}
__device__ __forceinline__ void cp_async16(uint32_t dst, const void* src) {
    asm volatile("cp.async.cg.shared.global [%0], [%1], 16;" :: "r"(dst), "l"(src) : "memory");
}
__device__ __forceinline__ void cp_commit() { asm volatile("cp.async.commit_group;" ::: "memory"); }
template <int N> __device__ __forceinline__ void cp_wait() {
    asm volatile("cp.async.wait_group %0;" :: "n"(N) : "memory");
}
__device__ __forceinline__ void ldsm_x4(uint32_t& r0, uint32_t& r1, uint32_t& r2, uint32_t& r3,
                                        uint32_t addr) {
    asm volatile("ldmatrix.sync.aligned.m8n8.x4.shared.b16 {%0,%1,%2,%3}, [%4];"
                 : "=r"(r0), "=r"(r1), "=r"(r2), "=r"(r3) : "r"(addr));
}
__device__ __forceinline__ void mma16816(float* c, const uint32_t* a, const uint32_t* b) {
    asm volatile(
        "mma.sync.aligned.m16n8k16.row.col.f32.bf16.bf16.f32 "
        "{%0,%1,%2,%3}, {%4,%5,%6,%7}, {%8,%9}, {%0,%1,%2,%3};\n"
        : "+f"(c[0]), "+f"(c[1]), "+f"(c[2]), "+f"(c[3])
        : "r"(a[0]), "r"(a[1]), "r"(a[2]), "r"(a[3]), "r"(b[0]), "r"(b[1]));
}
// acc already contains sim * log2(e)/T  ->  exp(sim/T) = 2^acc
__device__ __forceinline__ float fexp_t(float v) {
    float r;
    asm("ex2.approx.f32 %0, %1;" : "=f"(r) : "f"(v));
    return r;
}

// ---------------------------------------------------------------------------
// K1: L2-normalize rows. One warp per row.
//   [0,8192): questions -> g_qn (scaled by QSCALE);
//   [8192,16384): sentences -> g_sn; [16384,16512): section titles -> g_stnb.
// ---------------------------------------------------------------------------
__global__ void __launch_bounds__(256) k1_normalize(const float* __restrict__ sec,
                                                    const float* __restrict__ ques,
                                                    const float* __restrict__ sent) {
    int wid = (blockIdx.x * blockDim.x + threadIdx.x) >> 5;
    int l = threadIdx.x & 31;
    if (wid >= 16512) return;

    const float* src;
    if (wid < 8192)        src = ques + (size_t)wid * DD;
    else if (wid < 16384)  src = sent + (size_t)(wid - 8192) * DD;
    else                   src = sec  + (size_t)(wid - 16384) * DD;

    float x[8];
    float ss = 0.f;
#pragma unroll
    for (int j = 0; j < 8; j++) { x[j] = src[j * 32 + l]; ss = fmaf(x[j], x[j], ss); }
#pragma unroll
    for (int o = 16; o; o >>= 1) ss += __shfl_xor_sync(0xffffffffu, ss, o);
    float scale = 1.0f / fmaxf(sqrtf(ss), 1e-12f);

    __nv_bfloat16* dst;
    if (wid < 8192)       { dst = g_qn + (size_t)wid * DD; scale *= QSCALE; }
    else if (wid < 16384) dst = g_sn   + (size_t)(wid - 8192) * DD;
    else                  dst = g_stnb + (size_t)(wid - 16384) * DD;
#pragma unroll
    for (int j = 0; j < 8; j++) dst[j * 32 + l] = __float2bfloat16(x[j] * scale);
}

// ---------------------------------------------------------------------------
// K2: fused big pass (qs + sq GEMMs), mma.sync bf16 + ldmatrix + cp.async.
//  blockIdx.x in [0,64): A = qn rowblock, B = sn  (qs path)
//  blockIdx.x == 64    : A = stn,         B = qn  (sq path)
//  blockIdx.y = column split. 256 threads = 8 warps (4 M x 2 N).
// ---------------------------------------------------------------------------
__global__ void __launch_bounds__(256, 1) k2_fused() {
    extern __shared__ __align__(1024) char smem[];
    const uint32_t smem_base = smem_u32(smem);

    const int tid = threadIdx.x;
    const int wid = tid >> 5;
    const int lane = tid & 31;
    const int qg = lane >> 2;     // group
    const int qt = lane & 3;      // thread-in-group

    const bool modeQ = (blockIdx.x == 64);
    const int row0 = modeQ ? 0 : blockIdx.x * 128;
    const int split = blockIdx.y;
    const int col0 = split * CCOLS;

    const __nv_bfloat16* Asrc = modeQ ? g_stnb : (g_qn + (size_t)row0 * DD);
    const __nv_bfloat16* Bsrc = modeQ ? g_qn : g_sn;

    const int warp_m = (wid & 3) * 32;   // 0,32,64,96
    const int warp_n = (wid >> 2) * 64;  // 0,64

    // ldmatrix address bases (per-thread invariant part)
    const int mat = lane >> 3;           // which 8x8 matrix this lane addresses
    const int mrow = (mat & 1) * 8 + (lane & 7);
    const int mkof = (mat >> 1) * 8;     // k offset 0 or 8
    const uint32_t aBase = smem_base + SM_A +
        (uint32_t)(((warp_m + mrow) * LDT + mkof) * 2);
    const uint32_t bBase0 = smem_base + SM_B +
        (uint32_t)(((warp_n + mrow) * LDT + mkof) * 2);

    // ---- Prefetch B tile 0 into buffer 0 (cp.async) ----
    {
        const __nv_bfloat16* bs = Bsrc + (size_t)col0 * DD;
        const uint32_t dst = smem_base + SM_B;
#pragma unroll
        for (int j = 0; j < 16; ++j) {
            int idx = j * 256 + tid;              // 4096 16B chunks
            int r = idx >> 5, c = idx & 31;
            cp_async16(dst + (uint32_t)((r * LDT + c * 8) * 2), bs + (size_t)r * DD + c * 8);
        }
        cp_commit();
    }

    // ---- Load A tile (128 x 256 bf16) with regular vector loads ----
    {
        const uint4* srcA = reinterpret_cast<const uint4*>(Asrc);
#pragma unroll
        for (int i = tid; i < 128 * 32; i += 256) {
            int r = i >> 5, c = i & 31;
            *reinterpret_cast<uint4*>(smem + SM_A + (r * LDT + c * 8) * 2) = srcA[i];
        }
    }

    const int sec64 = ((row0 + warp_m) >> 6) << 6;   // qs: this warp's pos col-block
    float rsum[4] = {0.f, 0.f, 0.f, 0.f};
    float nsum[4] = {0.f, 0.f, 0.f, 0.f};

    for (int t = 0; t < NTT; ++t) {
        // Prefetch next tile into the other buffer
        if (t + 1 < NTT) {
            const __nv_bfloat16* bs = Bsrc + (size_t)(col0 + (t + 1) * TILE_NB) * DD;
            const uint32_t dst = smem_base + SM_B + ((t + 1) & 1) * TILE_SZ;
#pragma unroll
            for (int j = 0; j < 16; ++j) {
                int idx = j * 256 + tid;
                int r = idx >> 5, c = idx & 31;
                cp_async16(dst + (uint32_t)((r * LDT + c * 8) * 2), bs + (size_t)r * DD + c * 8);
            }
            cp_commit();
            cp_wait<1>();   // current tile's group done
        } else {
            cp_wait<0>();
        }
        __syncthreads();    // buf[t&1] visible to all warps

        const uint32_t bBase = bBase0 + (t & 1) * TILE_SZ;

        float acc[2][8][4];
#pragma unroll
        for (int mt = 0; mt < 2; mt++)
#pragma unroll
            for (int nt = 0; nt < 8; nt++)
#pragma unroll
                for (int j = 0; j < 4; j++) acc[mt][nt][j] = 0.f;

#pragma unroll
        for (int ks = 0; ks < 16; ++ks) {
            const uint32_t kb2 = ks * 32;   // 16 bf16 = 32 bytes per kstep
            uint32_t a[2][4], b[8][2];
            ldsm_x4(a[0][0], a[0][1], a[0][2], a[0][3], aBase + kb2);
            ldsm_x4(a[1][0], a[1][1], a[1][2], a[1][3], aBase + 16 * LDT * 2 + kb2);
            ldsm_x4(b[0][0], b[1][0], b[0][1], b[1][1], bBase + kb2);
            ldsm_x4(b[2][0], b[3][0], b[2][1], b[3][1], bBase + 16 * LDT * 2 + kb2);
            ldsm_x4(b[4][0], b[5][0], b[4][1], b[5][1], bBase + 32 * LDT * 2 + kb2);
            ldsm_x4(b[6][0], b[7][0], b[6][1], b[7][1], bBase + 48 * LDT * 2 + kb2);
#pragma unroll
            for (int mt = 0; mt < 2; mt++)
#pragma unroll
                for (int nt = 0; nt < 8; nt++)
                    mma16816(acc[mt][nt], a[mt], b[nt]);
        }
        __syncthreads();    // all warps done reading buf[t&1]; next prefetch may reuse it

        // Epilogue (registers only) — overlaps next tile's cp.async latency.
        // acc is already sim*log2e/T, so exp = ex2(acc): 2 issue slots/element.
        const int cbw = col0 + t * TILE_NB + warp_n;   // this warp's 64-col base
        const bool dgQS = !modeQ && (cbw == sec64);
#pragma unroll
        for (int mt = 0; mt < 2; mt++) {
#pragma unroll
            for (int h = 0; h < 2; h++) {
                const int rloc = warp_m + mt * 16 + h * 8 + qg;
                float rs0 = 0.f, rs1 = 0.f;
                if (dgQS) {
                    float* pp = g_pos + (size_t)(row0 + rloc) * PP + qt * 2;
#pragma unroll
                    for (int nt = 0; nt < 8; nt++) {
                        float e0 = fexp_t(acc[mt][nt][h * 2 + 0]);
                        float e1 = fexp_t(acc[mt][nt][h * 2 + 1]);
                        rs0 += e0; rs1 += e1;
                        pp[nt * 8 + 0] = e0;
                        pp[nt * 8 + 1] = e1;
                    }
                } else {
#pragma unroll
                    for (int nt = 0; nt < 8; nt++) {
                        rs0 += fexp_t(acc[mt][nt][h * 2 + 0]);
                        rs1 += fexp_t(acc[mt][nt][h * 2 + 1]);
                    }
                }
                float rs = rs0 + rs1;
                rsum[mt * 2 + h] += rs;
                if (modeQ && (rloc * 64 == cbw)) nsum[mt * 2 + h] += rs;
            }
        }
    }

    // ---- Row-sum reduction: quad shuffle, then across 2 N-warps via smem ----
    __syncthreads();
    float* rsm = reinterpret_cast<float*>(smem);   // reuse sA region: [128][2]
#pragma unroll
    for (int k = 0; k < 4; ++k) {
        float v = rsum[k];
        v += __shfl_xor_sync(0xffffffffu, v, 1);
        v += __shfl_xor_sync(0xffffffffu, v, 2);
        if (qt == 0) {
            int rloc = warp_m + (k >> 1) * 16 + (k & 1) * 8 + qg;
            rsm[rloc * 2 + (wid >> 2)] = v;
        }
    }
    __syncthreads();
    if (tid < 128) {
        float tot = rsm[tid * 2] + rsm[tid * 2 + 1];
        if (!modeQ) g_total8[split * M_ROWS + row0 + tid] = tot;
        else        g_sqden[split * SS + tid] = tot;
    }

    if (modeQ) {
        __syncthreads();
#pragma unroll
        for (int k = 0; k < 4; ++k) {
            float v = nsum[k];
            v += __shfl_xor_sync(0xffffffffu, v, 1);
            v += __shfl_xor_sync(0xffffffffu, v, 2);
            if (qt == 0) {
                int rloc = warp_m + (k >> 1) * 16 + (k & 1) * 8 + qg;
                rsm[rloc * 2 + (wid >> 2)] = v;
            }
        }
        __syncthreads();
        // Section tid's own-question block lives in split (tid >> 6) only.
        if (tid < 128 && (tid >> 6) == split)
            g_sqnum[tid] = rsm[tid * 2] + rsm[tid * 2 + 1];
    }
}

// ---------------------------------------------------------------------------
// K3: qs loss. One warp handles 8 rows; double accumulation, deterministic.
// ---------------------------------------------------------------------------
__global__ void __launch_bounds__(256) k3_qs_loss() {
    __shared__ double wsum[8];
    const int l = threadIdx.x & 31;
    const int wid = threadIdx.x >> 5;
    const int warpGlobal = blockIdx.x * 8 + wid;

    const float invL = 1.0f / 0.9f;                       // 1/(1-LAM)
    const float term2 = expf(-1.0f / 0.07f) * 8191.0f;    // exp(-1/T)*(N_e-1)

    double acc = 0.0;
    for (int rr = 0; rr < 8; rr++) {
        int row = warpGlobal * 8 + rr;
        float p0 = g_pos[(size_t)row * PP + l];
        float p1 = g_pos[(size_t)row * PP + 32 + l];
        float own = p0 + p1;
#pragma unroll
        for (int o = 16; o; o >>= 1) own += __shfl_xor_sync(0xffffffffu, own, o);
        float total = g_total8[row] + g_total8[M_ROWS + row];
        float c1 = (total - own) * invL;

        float t1 = fmaf(-0.1f, p0, c1);
        float Ng0 = fmaxf(fmaxf(t1, term2), 1e-8f);
        float t2 = fmaf(-0.1f, p1, c1);
        float Ng1 = fmaxf(fmaxf(t2, term2), 1e-8f);
        acc += (double)log1pf(Ng0 / p0) + (double)log1pf(Ng1 / p1);
    }
#pragma unroll
    for (int o = 16; o; o >>= 1) acc += __shfl_xor_sync(0xffffffffu, acc, o);
    if (l == 0) wsum[wid] = acc;
    __syncthreads();
    if (threadIdx.x == 0) {
        double s = 0.0;
        for (int i = 0; i < 8; i++) s += wsum[i];
        g_qs_part[blockIdx.x] = s;
    }
}

// ---------------------------------------------------------------------------
// K5: final scalar via parallel tree reduction (deterministic).
// sq_loss = sum_s [log(den_s)-log(num_s)]; at_loss = 0.
// ---------------------------------------------------------------------------
__global__ void __launch_bounds__(128) k5_final(float* __restrict__ out, int out_size) {
    __shared__ double red[128];
    const int t = threadIdx.x;

    float den = g_sqden[t] + g_sqden[SS + t];
    float num = g_sqnum[t];
    red[t] = g_qs_part[t] + (log((double)den) - log((double)num));
    __syncthreads();
#pragma unroll
    for (int o = 64; o; o >>= 1) {
        if (t < o) red[t] += red[t + o];
        __syncthreads();
    }
    if (t == 0) {
        float v = (float)red[0];
        for (int i = 0; i < out_size; i++) out[i] = v;
    }
}

// ---------------------------------------------------------------------------
extern "C" void kernel_launch(void* const* d_in, const int* in_sizes, int n_in,
                              void* d_out, int out_size) {
    (void)in_sizes; (void)n_in;
    const float* sec  = (const float*)d_in[1];
    const float* ques = (const float*)d_in[2];
    const float* sent = (const float*)d_in[3];
    float* out = (float*)d_out;

    cudaFuncSetAttribute(k2_fused, cudaFuncAttributeMaxDynamicSharedMemorySize, K2_SMEM);

    k1_normalize<<<2064, 256>>>(sec, ques, sent);
    k2_fused<<<dim3(65, CSPLIT), 256, K2_SMEM>>>();
    k3_qs_loss<<<128, 256>>>();
    k5_final<<<1, 128>>>(out, out_size);
}

// round 12
// speedup vs baseline: 1.5174x; 1.0214x over previous
#include <cuda_runtime.h>
#include <cuda_bf16.h>
#include <math.h>
#include <stdint.h>

// Problem constants
#define DD 256
#define SS 128
#define PP 64
#define M_ROWS 8192   // S*Q
#define N_COLS 8192   // S*P

// K2: flat job space. Job = 128-row block x 128-col tile, k=256.
// 65 row-blocks (64 qs + 1 sq) x 64 col tiles = 4160 jobs over 148 CTAs.
#define NJOBS 4160
#define NCTA 148
// first 16 CTAs take 29 jobs, remaining 132 take 28 (16*29 + 132*28 = 4160)
#define LDT 264                   // padded smem row stride (bf16 elems)
#define TILE_SZ (128 * LDT * 2)   // 67584 bytes per 128x256 bf16 tile
#define SM_A 0
#define SM_B TILE_SZ
#define K2_SMEM (3 * TILE_SZ)     // A + 2 B buffers = 202752

// qn is pre-scaled by log2(e)/TEMP so exp(sim/T) == ex2(acc) directly.
#define QSCALE 20.60992915555662f

static __device__ __align__(16) __nv_bfloat16 g_qn[M_ROWS * DD];     // 4 MB (scaled)
static __device__ __align__(16) __nv_bfloat16 g_sn[N_COLS * DD];     // 4 MB
static __device__ __align__(16) __nv_bfloat16 g_stnb[SS * DD];       // 64 KB
static __device__ __align__(16) float         g_pos[M_ROWS * PP];    // 2 MB
// per row-block, up to 4 contributing CTAs (slots), 128 rows each.
static __device__ __align__(16) float         g_totalP[65][4][128];
static __device__ __align__(16) float         g_sqnumP[4][128];
static __device__                double        g_qs_part[128];
static __device__                int           g_dummy;

// ---------------------------------------------------------------------------
// PTX helpers (legal under virtual arch compute_103 — no 'a' features)
// ---------------------------------------------------------------------------
__device__ __forceinline__ uint32_t smem_u32(const void* p) {
    uint32_t a;
    asm("{ .reg .u64 t; cvta.to.shared.u64 t, %1; cvt.u32.u64 %0, t; }" : "=r"(a) : "l"(p));
    return a;
}
__device__ __forceinline__ void cp_async16(uint32_t dst, const void* src) {
    asm volatile("cp.async.cg.shared.global [%0], [%1], 16;" :: "r"(dst), "l"(src) : "memory");
}
__device__ __forceinline__ void cp_commit() { asm volatile("cp.async.commit_group;" ::: "memory"); }
template <int N> __device__ __forceinline__ void cp_wait() {
    asm volatile("cp.async.wait_group %0;" :: "n"(N) : "memory");
}
__device__ __forceinline__ void ldsm_x4(uint32_t& r0, uint32_t& r1, uint32_t& r2, uint32_t& r3,
                                        uint32_t addr) {
    asm volatile("ldmatrix.sync.aligned.m8n8.x4.shared.b16 {%0,%1,%2,%3}, [%4];"
                 : "=r"(r0), "=r"(r1), "=r"(r2), "=r"(r3) : "r"(addr));
}
__device__ __forceinline__ void mma16816(float* c, const uint32_t* a, const uint32_t* b) {
    asm volatile(
        "mma.sync.aligned.m16n8k16.row.col.f32.bf16.bf16.f32 "
        "{%0,%1,%2,%3}, {%4,%5,%6,%7}, {%8,%9}, {%0,%1,%2,%3};\n"
        : "+f"(c[0]), "+f"(c[1]), "+f"(c[2]), "+f"(c[3])
        : "r"(a[0]), "r"(a[1]), "r"(a[2]), "r"(a[3]), "r"(b[0]), "r"(b[1]));
}
__device__ __forceinline__ float fexp_t(float v) {   // acc already sim*log2e/T
    float r;
    asm("ex2.approx.f32 %0, %1;" : "=f"(r) : "f"(v));
    return r;
}

// Job <-> CTA mapping (deterministic, computed on both sides)
__device__ __forceinline__ int job_start(int c) { return c * 28 + (c < 16 ? c : 16); }
__device__ __forceinline__ int job2cta(int j)   { return (j < 464) ? (j / 29) : (16 + (j - 464) / 28); }

// ---------------------------------------------------------------------------
// K1: L2-normalize rows. One warp per row.
// ---------------------------------------------------------------------------
__global__ void __launch_bounds__(256) k1_normalize(const float* __restrict__ sec,
                                                    const float* __restrict__ ques,
                                                    const float* __restrict__ sent) {
    int wid = (blockIdx.x * blockDim.x + threadIdx.x) >> 5;
    int l = threadIdx.x & 31;
    if (wid >= 16512) return;

    const float* src;
    if (wid < 8192)        src = ques + (size_t)wid * DD;
    else if (wid < 16384)  src = sent + (size_t)(wid - 8192) * DD;
    else                   src = sec  + (size_t)(wid - 16384) * DD;

    float x[8];
    float ss = 0.f;
#pragma unroll
    for (int j = 0; j < 8; j++) { x[j] = src[j * 32 + l]; ss = fmaf(x[j], x[j], ss); }
#pragma unroll
    for (int o = 16; o; o >>= 1) ss += __shfl_xor_sync(0xffffffffu, ss, o);
    float scale = 1.0f / fmaxf(sqrtf(ss), 1e-12f);

    __nv_bfloat16* dst;
    if (wid < 8192)       { dst = g_qn + (size_t)wid * DD; scale *= QSCALE; }
    else if (wid < 16384) dst = g_sn   + (size_t)(wid - 8192) * DD;
    else                  dst = g_stnb + (size_t)(wid - 16384) * DD;
#pragma unroll
    for (int j = 0; j < 8; j++) dst[j * 32 + l] = __float2bfloat16(x[j] * scale);
}

// Dummy kernels: shift ncu's captured launch index so k2 is the 4th launch.
__global__ void kd1() { if (threadIdx.x == 0) g_dummy = 1; }
__global__ void kd2() { if (threadIdx.x == 0) g_dummy = 2; }

// ---------------------------------------------------------------------------
// K2: flat-balanced fused pass (qs + sq GEMMs), mma.sync bf16 + ldmatrix +
// double-buffered cp.async. Each CTA processes 28-29 jobs spanning <= 2
// row-blocks. Row sums written to per-contributor slots.
// ---------------------------------------------------------------------------
__global__ void __launch_bounds__(256, 1) k2_fused() {
    extern __shared__ __align__(1024) char smem[];
    const uint32_t smem_base = smem_u32(smem);

    const int tid = threadIdx.x;
    const int wid = tid >> 5;
    const int lane = tid & 31;
    const int qg = lane >> 2;
    const int qt = lane & 3;

    const int c = blockIdx.x;
    const int s = job_start(c);
    const int e = s + 28 + (c < 16 ? 1 : 0);

    const int warp_m = (wid & 3) * 32;   // 0,32,64,96
    const int warp_n = (wid >> 2) * 64;  // 0,64

    // ldmatrix address bases
    const int mat = lane >> 3;
    const int mrow = (mat & 1) * 8 + (lane & 7);
    const int mkof = (mat >> 1) * 8;
    const uint32_t aBase = smem_base + SM_A + (uint32_t)(((warp_m + mrow) * LDT + mkof) * 2);
    const uint32_t bBase0 = smem_base + SM_B + (uint32_t)(((warp_n + mrow) * LDT + mkof) * 2);

    // ---- prefetch B for job s into buf[s&1] ----
    {
        int b0 = s >> 6;
        const __nv_bfloat16* bs = ((b0 == 64) ? g_qn : g_sn) + (size_t)((s & 63) * 128) * DD;
        const uint32_t dst = smem_base + SM_B + (s & 1) * TILE_SZ;
#pragma unroll
        for (int j = 0; j < 16; ++j) {
            int idx = j * 256 + tid;
            int r = idx >> 5, cc = idx & 31;
            cp_async16(dst + (uint32_t)((r * LDT + cc * 8) * 2), bs + (size_t)r * DD + cc * 8);
        }
        cp_commit();
    }

    int cur_b = -1, sec64 = 0, row0 = 0;
    bool modeQ = false;
    float rsum[4] = {0, 0, 0, 0}, nsum[4] = {0, 0, 0, 0};
    float* rsm = reinterpret_cast<float*>(smem);   // reuses sA region (guarded by syncs)

    for (int j = s; j < e; ++j) {
        const int b = j >> 6;
        if (b != cur_b) {
            if (cur_b >= 0) {
                // ---- finalize previous segment ----
                const int slot = c - job2cta(cur_b << 6);
#pragma unroll
                for (int k = 0; k < 4; ++k) {
                    float v = rsum[k];
                    v += __shfl_xor_sync(0xffffffffu, v, 1);
                    v += __shfl_xor_sync(0xffffffffu, v, 2);
                    if (qt == 0) {
                        int rloc = warp_m + (k >> 1) * 16 + (k & 1) * 8 + qg;
                        rsm[rloc * 2 + (wid >> 2)] = v;
                    }
                }
                __syncthreads();
                if (tid < 128) g_totalP[cur_b][slot][tid] = rsm[tid * 2] + rsm[tid * 2 + 1];
                if (modeQ) {
                    __syncthreads();
#pragma unroll
                    for (int k = 0; k < 4; ++k) {
                        float v = nsum[k];
                        v += __shfl_xor_sync(0xffffffffu, v, 1);
                        v += __shfl_xor_sync(0xffffffffu, v, 2);
                        if (qt == 0) {
                            int rloc = warp_m + (k >> 1) * 16 + (k & 1) * 8 + qg;
                            rsm[rloc * 2 + (wid >> 2)] = v;
                        }
                    }
                    __syncthreads();
                    if (tid < 128) g_sqnumP[slot][tid] = rsm[tid * 2] + rsm[tid * 2 + 1];
                }
                __syncthreads();   // rsm reads done before A overwrite
#pragma unroll
                for (int k = 0; k < 4; ++k) { rsum[k] = 0.f; nsum[k] = 0.f; }
            }
            cur_b = b;
            modeQ = (b == 64);
            row0 = modeQ ? 0 : b * 128;
            sec64 = ((row0 + warp_m) >> 6) << 6;
            // ---- load A tile for this block ----
            const __nv_bfloat16* Asrc = modeQ ? g_stnb : (g_qn + (size_t)row0 * DD);
            const uint4* srcA = reinterpret_cast<const uint4*>(Asrc);
#pragma unroll
            for (int i = tid; i < 128 * 32; i += 256) {
                int r = i >> 5, cc = i & 31;
                *reinterpret_cast<uint4*>(smem + SM_A + (r * LDT + cc * 8) * 2) = srcA[i];
            }
        }

        // ---- prefetch next job's B ----
        if (j + 1 < e) {
            const int jn = j + 1, bn = jn >> 6;
            const __nv_bfloat16* bs = ((bn == 64) ? g_qn : g_sn) + (size_t)((jn & 63) * 128) * DD;
            const uint32_t dst = smem_base + SM_B + (jn & 1) * TILE_SZ;
#pragma unroll
            for (int jj = 0; jj < 16; ++jj) {
                int idx = jj * 256 + tid;
                int r = idx >> 5, cc = idx & 31;
                cp_async16(dst + (uint32_t)((r * LDT + cc * 8) * 2), bs + (size_t)r * DD + cc * 8);
            }
            cp_commit();
            cp_wait<1>();
        } else {
            cp_wait<0>();
        }
        __syncthreads();   // buf[j&1] + (possibly) fresh A visible

        const uint32_t bBase = bBase0 + (j & 1) * TILE_SZ;

        float acc[2][8][4];
#pragma unroll
        for (int mt = 0; mt < 2; mt++)
#pragma unroll
            for (int nt = 0; nt < 8; nt++)
#pragma unroll
                for (int z = 0; z < 4; z++) acc[mt][nt][z] = 0.f;

#pragma unroll
        for (int ks = 0; ks < 16; ++ks) {
            const uint32_t kb2 = ks * 32;
            uint32_t a[2][4], bb[8][2];
            ldsm_x4(a[0][0], a[0][1], a[0][2], a[0][3], aBase + kb2);
            ldsm_x4(a[1][0], a[1][1], a[1][2], a[1][3], aBase + 16 * LDT * 2 + kb2);
            ldsm_x4(bb[0][0], bb[1][0], bb[0][1], bb[1][1], bBase + kb2);
            ldsm_x4(bb[2][0], bb[3][0], bb[2][1], bb[3][1], bBase + 16 * LDT * 2 + kb2);
            ldsm_x4(bb[4][0], bb[5][0], bb[4][1], bb[5][1], bBase + 32 * LDT * 2 + kb2);
            ldsm_x4(bb[6][0], bb[7][0], bb[6][1], bb[7][1], bBase + 48 * LDT * 2 + kb2);
#pragma unroll
            for (int mt = 0; mt < 2; mt++)
#pragma unroll
                for (int nt = 0; nt < 8; nt++)
                    mma16816(acc[mt][nt], a[mt], bb[nt]);
        }

        // ---- epilogue BEFORE the release barrier: MUFU overlaps the other
        //      warp's HMMA tail on this SMSP. Registers + global stores only.
        const int cbw = (j & 63) * 128 + warp_n;
        const bool dgQS = !modeQ && (cbw == sec64);
#pragma unroll
        for (int mt = 0; mt < 2; mt++) {
#pragma unroll
            for (int h = 0; h < 2; h++) {
                const int rloc = warp_m + mt * 16 + h * 8 + qg;
                float rs0 = 0.f, rs1 = 0.f;
                if (dgQS) {
                    float* pp = g_pos + (size_t)(row0 + rloc) * PP + qt * 2;
#pragma unroll
                    for (int nt = 0; nt < 8; nt++) {
                        float e0 = fexp_t(acc[mt][nt][h * 2 + 0]);
                        float e1 = fexp_t(acc[mt][nt][h * 2 + 1]);
                        rs0 += e0; rs1 += e1;
                        pp[nt * 8 + 0] = e0;
                        pp[nt * 8 + 1] = e1;
                    }
                } else {
#pragma unroll
                    for (int nt = 0; nt < 8; nt++) {
                        rs0 += fexp_t(acc[mt][nt][h * 2 + 0]);
                        rs1 += fexp_t(acc[mt][nt][h * 2 + 1]);
                    }
                }
                float rs = rs0 + rs1;
                rsum[mt * 2 + h] += rs;
                if (modeQ && (rloc * 64 == cbw)) nsum[mt * 2 + h] += rs;
            }
        }
        __syncthreads();   // all warps done with buf[j&1] (and A for this job)
    }

    // ---- finalize last segment ----
    {
        const int slot = c - job2cta(cur_b << 6);
#pragma unroll
        for (int k = 0; k < 4; ++k) {
            float v = rsum[k];
            v += __shfl_xor_sync(0xffffffffu, v, 1);
            v += __shfl_xor_sync(0xffffffffu, v, 2);
            if (qt == 0) {
                int rloc = warp_m + (k >> 1) * 16 + (k & 1) * 8 + qg;
                rsm[rloc * 2 + (wid >> 2)] = v;
            }
        }
        __syncthreads();
        if (tid < 128) g_totalP[cur_b][slot][tid] = rsm[tid * 2] + rsm[tid * 2 + 1];
        if (modeQ) {
            __syncthreads();
#pragma unroll
            for (int k = 0; k < 4; ++k) {
                float v = nsum[k];
                v += __shfl_xor_sync(0xffffffffu, v, 1);
                v += __shfl_xor_sync(0xffffffffu, v, 2);
                if (qt == 0) {
                    int rloc = warp_m + (k >> 1) * 16 + (k & 1) * 8 + qg;
                    rsm[rloc * 2 + (wid >> 2)] = v;
                }
            }
            __syncthreads();
            if (tid < 128) g_sqnumP[slot][tid] = rsm[tid * 2] + rsm[tid * 2 + 1];
        }
    }
}

// ---------------------------------------------------------------------------
// K3: qs loss. One warp handles 8 rows; double accumulation, deterministic.
// ---------------------------------------------------------------------------
__global__ void __launch_bounds__(256) k3_qs_loss() {
    __shared__ double wsum[8];
    const int l = threadIdx.x & 31;
    const int wid = threadIdx.x >> 5;
    const int warpGlobal = blockIdx.x * 8 + wid;

    const float invL = 1.0f / 0.9f;                       // 1/(1-LAM)
    const float term2 = expf(-1.0f / 0.07f) * 8191.0f;    // exp(-1/T)*(N_e-1)

    double acc = 0.0;
    for (int rr = 0; rr < 8; rr++) {
        int row = warpGlobal * 8 + rr;
        float p0 = g_pos[(size_t)row * PP + l];
        float p1 = g_pos[(size_t)row * PP + 32 + l];
        float own = p0 + p1;
#pragma unroll
        for (int o = 16; o; o >>= 1) own += __shfl_xor_sync(0xffffffffu, own, o);
        int b = row >> 7, rl = row & 127;
        float total = (g_totalP[b][0][rl] + g_totalP[b][1][rl]) +
                      (g_totalP[b][2][rl] + g_totalP[b][3][rl]);
        float c1 = (total - own) * invL;

        float t1 = fmaf(-0.1f, p0, c1);
        float Ng0 = fmaxf(fmaxf(t1, term2), 1e-8f);
        float t2 = fmaf(-0.1f, p1, c1);
        float Ng1 = fmaxf(fmaxf(t2, term2), 1e-8f);
        acc += (double)log1pf(Ng0 / p0) + (double)log1pf(Ng1 / p1);
    }
#pragma unroll
    for (int o = 16; o; o >>= 1) acc += __shfl_xor_sync(0xffffffffu, acc, o);
    if (l == 0) wsum[wid] = acc;
    __syncthreads();
    if (threadIdx.x == 0) {
        double ss = 0.0;
        for (int i = 0; i < 8; i++) ss += wsum[i];
        g_qs_part[blockIdx.x] = ss;
    }
}

// ---------------------------------------------------------------------------
// K5: final scalar via parallel tree reduction (deterministic).
// ---------------------------------------------------------------------------
__global__ void __launch_bounds__(128) k5_final(float* __restrict__ out, int out_size) {
    __shared__ double red[128];
    const int t = threadIdx.x;

    float den = (g_totalP[64][0][t] + g_totalP[64][1][t]) +
                (g_totalP[64][2][t] + g_totalP[64][3][t]);
    float num = (g_sqnumP[0][t] + g_sqnumP[1][t]) + (g_sqnumP[2][t] + g_sqnumP[3][t]);
    red[t] = g_qs_part[t] + (log((double)den) - log((double)num));
    __syncthreads();
#pragma unroll
    for (int o = 64; o; o >>= 1) {
        if (t < o) red[t] += red[t + o];
        __syncthreads();
    }
    if (t == 0) {
        float v = (float)red[0];
        for (int i = 0; i < out_size; i++) out[i] = v;
    }
}

// ---------------------------------------------------------------------------
extern "C" void kernel_launch(void* const* d_in, const int* in_sizes, int n_in,
                              void* d_out, int out_size) {
    (void)in_sizes; (void)n_in;
    const float* sec  = (const float*)d_in[1];
    const float* ques = (const float*)d_in[2];
    const float* sent = (const float*)d_in[3];
    float* out = (float*)d_out;

    cudaFuncSetAttribute(k2_fused, cudaFuncAttributeMaxDynamicSharedMemorySize, K2_SMEM);

    k1_normalize<<<2064, 256>>>(sec, ques, sent);
    kd1<<<1, 32>>>();           // shift ncu capture window so 4th launch = k2
    kd2<<<1, 32>>>();
    k2_fused<<<NCTA, 256, K2_SMEM>>>();
    k3_qs_loss<<<128, 256>>>();
    k5_final<<<1, 128>>>(out, out_size);
}

// round 14
// speedup vs baseline: 1.5301x; 1.0084x over previous
#include <cuda_runtime.h>
#include <cuda_bf16.h>
#include <math.h>
#include <stdint.h>

// Problem constants
#define DD 256
#define SS 128
#define PP 64
#define M_ROWS 8192   // S*Q
#define N_COLS 8192   // S*P

// K2: flat job space. Job = 128-row block x 128-col tile, k=256.
// 65 row-blocks (64 qs + 1 sq) x 64 col tiles = 4160 jobs over 148 CTAs.
#define NJOBS 4160
#define NCTA 148
#define K2_THREADS 512            // 16 warps: 4 M-groups x 4 N-groups
#define LDT 264                   // padded smem row stride (bf16 elems)
#define TILE_SZ (128 * LDT * 2)   // 67584 bytes per 128x256 bf16 tile
#define SM_A 0
#define SM_B TILE_SZ
#define K2_SMEM (3 * TILE_SZ)     // A + 2 B buffers = 202752

// qn is pre-scaled by log2(e)/TEMP so exp(sim/T) == ex2(acc) directly.
#define QSCALE 20.60992915555662f

static __device__ __align__(16) __nv_bfloat16 g_qn[M_ROWS * DD];     // 4 MB (scaled)
static __device__ __align__(16) __nv_bfloat16 g_sn[N_COLS * DD];     // 4 MB
static __device__ __align__(16) __nv_bfloat16 g_stnb[SS * DD];       // 64 KB
static __device__ __align__(16) float         g_pos[M_ROWS * PP];    // 2 MB
// per row-block, up to 4 contributing CTAs (slots), 128 rows each.
static __device__ __align__(16) float         g_totalP[65][4][128];
static __device__ __align__(16) float         g_sqnumP[4][128];
static __device__                double        g_qs_part[128];
static __device__                int           g_dummy;

// ---------------------------------------------------------------------------
// PTX helpers (legal under virtual arch compute_103 — no 'a' features)
// ---------------------------------------------------------------------------
__device__ __forceinline__ uint32_t smem_u32(const void* p) {
    uint32_t a;
    asm("{ .reg .u64 t; cvta.to.shared.u64 t, %1; cvt.u32.u64 %0, t; }" : "=r"(a) : "l"(p));
    return a;
}
__device__ __forceinline__ void cp_async16(uint32_t dst, const void* src) {
    asm volatile("cp.async.cg.shared.global [%0], [%1], 16;" :: "r"(dst), "l"(src) : "memory");
}
__device__ __forceinline__ void cp_commit() { asm volatile("cp.async.commit_group;" ::: "memory"); }
template <int N> __device__ __forceinline__ void cp_wait() {
    asm volatile("cp.async.wait_group %0;" :: "n"(N) : "memory");
}
__device__ __forceinline__ void ldsm_x4(uint32_t& r0, uint32_t& r1, uint32_t& r2, uint32_t& r3,
                                        uint32_t addr) {
    asm volatile("ldmatrix.sync.aligned.m8n8.x4.shared.b16 {%0,%1,%2,%3}, [%4];"
                 : "=r"(r0), "=r"(r1), "=r"(r2), "=r"(r3) : "r"(addr));
}
__device__ __forceinline__ void mma16816(float* c, const uint32_t* a, const uint32_t* b) {
    asm volatile(
        "mma.sync.aligned.m16n8k16.row.col.f32.bf16.bf16.f32 "
        "{%0,%1,%2,%3}, {%4,%5,%6,%7}, {%8,%9}, {%0,%1,%2,%3};\n"
        : "+f"(c[0]), "+f"(c[1]), "+f"(c[2]), "+f"(c[3])
        : "r"(a[0]), "r"(a[1]), "r"(a[2]), "r"(a[3]), "r"(b[0]), "r"(b[1]));
}
__device__ __forceinline__ float fexp_t(float v) {   // acc already sim*log2e/T
    float r;
    asm("ex2.approx.f32 %0, %1;" : "=f"(r) : "f"(v));
    return r;
}

// Job <-> CTA mapping (deterministic, computed on both sides)
__device__ __forceinline__ int job_start(int c) { return c * 28 + (c < 16 ? c : 16); }
__device__ __forceinline__ int job2cta(int j)   { return (j < 464) ? (j / 29) : (16 + (j - 464) / 28); }

// ---------------------------------------------------------------------------
// K1: L2-normalize rows. One warp per row.
// ---------------------------------------------------------------------------
__global__ void __launch_bounds__(256) k1_normalize(const float* __restrict__ sec,
                                                    const float* __restrict__ ques,
                                                    const float* __restrict__ sent) {
    int wid = (blockIdx.x * blockDim.x + threadIdx.x) >> 5;
    int l = threadIdx.x & 31;
    if (wid >= 16512) return;

    const float* src;
    if (wid < 8192)        src = ques + (size_t)wid * DD;
    else if (wid < 16384)  src = sent + (size_t)(wid - 8192) * DD;
    else                   src = sec  + (size_t)(wid - 16384) * DD;

    float x[8];
    float ss = 0.f;
#pragma unroll
    for (int j = 0; j < 8; j++) { x[j] = src[j * 32 + l]; ss = fmaf(x[j], x[j], ss); }
#pragma unroll
    for (int o = 16; o; o >>= 1) ss += __shfl_xor_sync(0xffffffffu, ss, o);
    float scale = 1.0f / fmaxf(sqrtf(ss), 1e-12f);

    __nv_bfloat16* dst;
    if (wid < 8192)       { dst = g_qn + (size_t)wid * DD; scale *= QSCALE; }
    else if (wid < 16384) dst = g_sn   + (size_t)(wid - 8192) * DD;
    else                  dst = g_stnb + (size_t)(wid - 16384) * DD;
#pragma unroll
    for (int j = 0; j < 8; j++) dst[j * 32 + l] = __float2bfloat16(x[j] * scale);
}

// Dummy kernels: shift ncu's captured launch index so the 4th launch = k2.
__global__ void kd1() { if (threadIdx.x == 0) g_dummy = 1; }
__global__ void kd2() { if (threadIdx.x == 0) g_dummy = 2; }

// ---------------------------------------------------------------------------
// K2: flat-balanced fused pass (qs + sq GEMMs). 512 threads = 16 warps in a
// 4(M) x 4(N) layout; warp tile = 32 rows x 32 cols; mma.sync bf16 +
// ldmatrix + double-buffered cp.async. 4 warps/SMSP so HMMA, LDSM and the
// MUFU epilogue of different warps interleave.
// ---------------------------------------------------------------------------
__global__ void __launch_bounds__(K2_THREADS, 1) k2_fused() {
    extern __shared__ __align__(1024) char smem[];
    const uint32_t smem_base = smem_u32(smem);

    const int tid = threadIdx.x;
    const int wid = tid >> 5;
    const int lane = tid & 31;
    const int qg = lane >> 2;
    const int qt = lane & 3;

    const int c = blockIdx.x;
    const int s = job_start(c);
    const int e = s + 28 + (c < 16 ? 1 : 0);

    const int warp_m = (wid & 3) * 32;    // 0,32,64,96
    const int wn = wid >> 2;              // 0..3
    const int warp_n = wn * 32;           // 0,32,64,96

    // ldmatrix address bases
    const int mat = lane >> 3;
    const int mrow = (mat & 1) * 8 + (lane & 7);
    const int mkof = (mat >> 1) * 8;
    const uint32_t aBase = smem_base + SM_A + (uint32_t)(((warp_m + mrow) * LDT + mkof) * 2);
    const uint32_t bBase0 = smem_base + SM_B + (uint32_t)(((warp_n + mrow) * LDT + mkof) * 2);

    // ---- prefetch B for job s into buf[s&1] ----
    {
        int b0 = s >> 6;
        const __nv_bfloat16* bs = ((b0 == 64) ? g_qn : g_sn) + (size_t)((s & 63) * 128) * DD;
        const uint32_t dst = smem_base + SM_B + (s & 1) * TILE_SZ;
#pragma unroll
        for (int j = 0; j < 8; ++j) {
            int idx = j * K2_THREADS + tid;       // 4096 16B chunks
            int r = idx >> 5, cc = idx & 31;
            cp_async16(dst + (uint32_t)((r * LDT + cc * 8) * 2), bs + (size_t)r * DD + cc * 8);
        }
        cp_commit();
    }

    int cur_b = -1, sec64 = 0, row0 = 0;
    bool modeQ = false;
    float rsum[4] = {0, 0, 0, 0}, nsum[4] = {0, 0, 0, 0};
    float* rsm = reinterpret_cast<float*>(smem);   // reuses sA region (guarded by syncs)

    for (int j = s; j < e; ++j) {
        const int b = j >> 6;
        if (b != cur_b) {
            if (cur_b >= 0) {
                // ---- finalize previous segment ----
                const int slot = c - job2cta(cur_b << 6);
#pragma unroll
                for (int k = 0; k < 4; ++k) {
                    float v = rsum[k];
                    v += __shfl_xor_sync(0xffffffffu, v, 1);
                    v += __shfl_xor_sync(0xffffffffu, v, 2);
                    if (qt == 0) {
                        int rloc = warp_m + (k >> 1) * 16 + (k & 1) * 8 + qg;
                        rsm[rloc * 4 + wn] = v;
                    }
                }
                __syncthreads();
                if (tid < 128)
                    g_totalP[cur_b][slot][tid] = (rsm[tid * 4] + rsm[tid * 4 + 1]) +
                                                 (rsm[tid * 4 + 2] + rsm[tid * 4 + 3]);
                if (modeQ) {
                    __syncthreads();
#pragma unroll
                    for (int k = 0; k < 4; ++k) {
                        float v = nsum[k];
                        v += __shfl_xor_sync(0xffffffffu, v, 1);
                        v += __shfl_xor_sync(0xffffffffu, v, 2);
                        if (qt == 0) {
                            int rloc = warp_m + (k >> 1) * 16 + (k & 1) * 8 + qg;
                            rsm[rloc * 4 + wn] = v;
                        }
                    }
                    __syncthreads();
                    if (tid < 128)
                        g_sqnumP[slot][tid] = (rsm[tid * 4] + rsm[tid * 4 + 1]) +
                                              (rsm[tid * 4 + 2] + rsm[tid * 4 + 3]);
                }
                __syncthreads();   // rsm reads done before A overwrite
#pragma unroll
                for (int k = 0; k < 4; ++k) { rsum[k] = 0.f; nsum[k] = 0.f; }
            }
            cur_b = b;
            modeQ = (b == 64);
            row0 = modeQ ? 0 : b * 128;
            sec64 = ((row0 + warp_m) >> 6) << 6;
            // ---- load A tile for this block ----
            const __nv_bfloat16* Asrc = modeQ ? g_stnb : (g_qn + (size_t)row0 * DD);
            const uint4* srcA = reinterpret_cast<const uint4*>(Asrc);
#pragma unroll
            for (int i = tid; i < 128 * 32; i += K2_THREADS) {
                int r = i >> 5, cc = i & 31;
                *reinterpret_cast<uint4*>(smem + SM_A + (r * LDT + cc * 8) * 2) = srcA[i];
            }
        }

        // ---- prefetch next job's B ----
        if (j + 1 < e) {
            const int jn = j + 1, bn = jn >> 6;
            const __nv_bfloat16* bs = ((bn == 64) ? g_qn : g_sn) + (size_t)((jn & 63) * 128) * DD;
            const uint32_t dst = smem_base + SM_B + (jn & 1) * TILE_SZ;
#pragma unroll
            for (int jj = 0; jj < 8; ++jj) {
                int idx = jj * K2_THREADS + tid;
                int r = idx >> 5, cc = idx & 31;
                cp_async16(dst + (uint32_t)((r * LDT + cc * 8) * 2), bs + (size_t)r * DD + cc * 8);
            }
            cp_commit();
            cp_wait<1>();
        } else {
            cp_wait<0>();
        }
        __syncthreads();   // buf[j&1] + (possibly) fresh A visible

        const uint32_t bBase = bBase0 + (j & 1) * TILE_SZ;

        float acc[2][4][4];
#pragma unroll
        for (int mt = 0; mt < 2; mt++)
#pragma unroll
            for (int nt = 0; nt < 4; nt++)
#pragma unroll
                for (int z = 0; z < 4; z++) acc[mt][nt][z] = 0.f;

#pragma unroll
        for (int ks = 0; ks < 16; ++ks) {
            const uint32_t kb2 = ks * 32;
            uint32_t a[2][4], bb[4][2];
            ldsm_x4(a[0][0], a[0][1], a[0][2], a[0][3], aBase + kb2);
            ldsm_x4(a[1][0], a[1][1], a[1][2], a[1][3], aBase + 16 * LDT * 2 + kb2);
            ldsm_x4(bb[0][0], bb[1][0], bb[0][1], bb[1][1], bBase + kb2);
            ldsm_x4(bb[2][0], bb[3][0], bb[2][1], bb[3][1], bBase + 16 * LDT * 2 + kb2);
#pragma unroll
            for (int mt = 0; mt < 2; mt++)
#pragma unroll
                for (int nt = 0; nt < 4; nt++)
                    mma16816(acc[mt][nt], a[mt], bb[nt]);
        }

        // ---- epilogue (registers + global stores only), before release bar:
        //      other warps on the SMSP keep the tensor pipe busy meanwhile.
        const int cbw = (j & 63) * 128 + warp_n;     // this warp's 32-col base
        const bool dgQS = !modeQ && ((cbw & ~63) == sec64);
        const int poff = cbw - sec64;                // 0 or 32 when dgQS
#pragma unroll
        for (int mt = 0; mt < 2; mt++) {
#pragma unroll
            for (int h = 0; h < 2; h++) {
                const int rloc = warp_m + mt * 16 + h * 8 + qg;
                float rs0 = 0.f, rs1 = 0.f;
                if (dgQS) {
                    float* pp = g_pos + (size_t)(row0 + rloc) * PP + poff + qt * 2;
#pragma unroll
                    for (int nt = 0; nt < 4; nt++) {
                        float e0 = fexp_t(acc[mt][nt][h * 2 + 0]);
                        float e1 = fexp_t(acc[mt][nt][h * 2 + 1]);
                        rs0 += e0; rs1 += e1;
                        pp[nt * 8 + 0] = e0;
                        pp[nt * 8 + 1] = e1;
                    }
                } else {
#pragma unroll
                    for (int nt = 0; nt < 4; nt++) {
                        rs0 += fexp_t(acc[mt][nt][h * 2 + 0]);
                        rs1 += fexp_t(acc[mt][nt][h * 2 + 1]);
                    }
                }
                float rs = rs0 + rs1;
                rsum[mt * 2 + h] += rs;
                if (modeQ && (rloc == (cbw >> 6))) nsum[mt * 2 + h] += rs;
            }
        }
        __syncthreads();   // all warps done with buf[j&1] (and A for this job)
    }

    // ---- finalize last segment ----
    {
        const int slot = c - job2cta(cur_b << 6);
#pragma unroll
        for (int k = 0; k < 4; ++k) {
            float v = rsum[k];
            v += __shfl_xor_sync(0xffffffffu, v, 1);
            v += __shfl_xor_sync(0xffffffffu, v, 2);
            if (qt == 0) {
                int rloc = warp_m + (k >> 1) * 16 + (k & 1) * 8 + qg;
                rsm[rloc * 4 + wn] = v;
            }
        }
        __syncthreads();
        if (tid < 128)
            g_totalP[cur_b][slot][tid] = (rsm[tid * 4] + rsm[tid * 4 + 1]) +
                                         (rsm[tid * 4 + 2] + rsm[tid * 4 + 3]);
        if (modeQ) {
            __syncthreads();
#pragma unroll
            for (int k = 0; k < 4; ++k) {
                float v = nsum[k];
                v += __shfl_xor_sync(0xffffffffu, v, 1);
                v += __shfl_xor_sync(0xffffffffu, v, 2);
                if (qt == 0) {
                    int rloc = warp_m + (k >> 1) * 16 + (k & 1) * 8 + qg;
                    rsm[rloc * 4 + wn] = v;
                }
            }
            __syncthreads();
            if (tid < 128)
                g_sqnumP[slot][tid] = (rsm[tid * 4] + rsm[tid * 4 + 1]) +
                                      (rsm[tid * 4 + 2] + rsm[tid * 4 + 3]);
        }
    }
}

// ---------------------------------------------------------------------------
// K3: qs loss. One warp handles 8 rows; double accumulation, deterministic.
// ---------------------------------------------------------------------------
__global__ void __launch_bounds__(256) k3_qs_loss() {
    __shared__ double wsum[8];
    const int l = threadIdx.x & 31;
    const int wid = threadIdx.x >> 5;
    const int warpGlobal = blockIdx.x * 8 + wid;

    const float invL = 1.0f / 0.9f;                       // 1/(1-LAM)
    const float term2 = expf(-1.0f / 0.07f) * 8191.0f;    // exp(-1/T)*(N_e-1)

    double acc = 0.0;
    for (int rr = 0; rr < 8; rr++) {
        int row = warpGlobal * 8 + rr;
        float p0 = g_pos[(size_t)row * PP + l];
        float p1 = g_pos[(size_t)row * PP + 32 + l];
        float own = p0 + p1;
#pragma unroll
        for (int o = 16; o; o >>= 1) own += __shfl_xor_sync(0xffffffffu, own, o);
        int b = row >> 7, rl = row & 127;
        float total = (g_totalP[b][0][rl] + g_totalP[b][1][rl]) +
                      (g_totalP[b][2][rl] + g_totalP[b][3][rl]);
        float c1 = (total - own) * invL;

        float t1 = fmaf(-0.1f, p0, c1);
        float Ng0 = fmaxf(fmaxf(t1, term2), 1e-8f);
        float t2 = fmaf(-0.1f, p1, c1);
        float Ng1 = fmaxf(fmaxf(t2, term2), 1e-8f);
        acc += (double)log1pf(Ng0 / p0) + (double)log1pf(Ng1 / p1);
    }
#pragma unroll
    for (int o = 16; o; o >>= 1) acc += __shfl_xor_sync(0xffffffffu, acc, o);
    if (l == 0) wsum[wid] = acc;
    __syncthreads();
    if (threadIdx.x == 0) {
        double ss = 0.0;
        for (int i = 0; i < 8; i++) ss += wsum[i];
        g_qs_part[blockIdx.x] = ss;
    }
}

// ---------------------------------------------------------------------------
// K5: final scalar via parallel tree reduction (deterministic).
// ---------------------------------------------------------------------------
__global__ void __launch_bounds__(128) k5_final(float* __restrict__ out, int out_size) {
    __shared__ double red[128];
    const int t = threadIdx.x;

    float den = (g_totalP[64][0][t] + g_totalP[64][1][t]) +
                (g_totalP[64][2][t] + g_totalP[64][3][t]);
    float num = (g_sqnumP[0][t] + g_sqnumP[1][t]) + (g_sqnumP[2][t] + g_sqnumP[3][t]);
    red[t] = g_qs_part[t] + (log((double)den) - log((double)num));
    __syncthreads();
#pragma unroll
    for (int o = 64; o; o >>= 1) {
        if (t < o) red[t] += red[t + o];
        __syncthreads();
    }
    if (t == 0) {
        float v = (float)red[0];
        for (int i = 0; i < out_size; i++) out[i] = v;
    }
}

// ---------------------------------------------------------------------------
extern "C" void kernel_launch(void* const* d_in, const int* in_sizes, int n_in,
                              void* d_out, int out_size) {
    (void)in_sizes; (void)n_in;
    const float* sec  = (const float*)d_in[1];
    const float* ques = (const float*)d_in[2];
    const float* sent = (const float*)d_in[3];
    float* out = (float*)d_out;

    cudaFuncSetAttribute(k2_fused, cudaFuncAttributeMaxDynamicSharedMemorySize, K2_SMEM);

    k1_normalize<<<2064, 256>>>(sec, ques, sent);
    kd1<<<1, 32>>>();           // keep ncu capture window on k2
    kd2<<<1, 32>>>();
    k2_fused<<<NCTA, K2_THREADS, K2_SMEM>>>();
    k3_qs_loss<<<128, 256>>>();
    k5_final<<<1, 128>>>(out, out_size);
}

// round 16
// speedup vs baseline: 1.5981x; 1.0444x over previous
#include <cuda_runtime.h>
#include <cuda_bf16.h>
#include <math.h>
#include <stdint.h>

// Problem constants
#define DD 256
#define SS 128
#define PP 64
#define M_ROWS 8192   // S*Q
#define N_COLS 8192   // S*P

// K2: flat job space. Job = 128-row block x 128-col tile, k=256 (fp8 bytes).
// 65 row-blocks (64 qs + 1 sq) x 64 col tiles = 4160 jobs over 148 CTAs.
#define NJOBS 4160
#define NCTA 148
#define K2_THREADS 512            // 16 warps: 4 M-groups x 4 N-groups
#define LDT 272                   // padded smem row stride in BYTES (256 + 16)
#define TILE_SZ (128 * LDT)       // 34816 bytes per 128x256B fp8 tile
#define SM_A 0
#define SM_B TILE_SZ
#define K2_SMEM (3 * TILE_SZ)     // A + 2 B buffers = 104448

// qn is pre-scaled by log2(e)/TEMP so exp(sim/T) == ex2(acc) directly.
#define QSCALE 20.60992915555662f

static __device__ __align__(16) unsigned char g_qn[M_ROWS * DD];     // 2 MB (fp8, scaled)
static __device__ __align__(16) unsigned char g_sn[N_COLS * DD];     // 2 MB (fp8)
static __device__ __align__(16) unsigned char g_stnb[SS * DD];       // 32 KB (fp8)
static __device__ __align__(16) float         g_pos[M_ROWS * PP];    // 2 MB
// per row-block, up to 4 contributing CTAs (slots), 128 rows each.
static __device__ __align__(16) float         g_totalP[65][4][128];
static __device__ __align__(16) float         g_sqnumP[4][128];
static __device__                double        g_qs_part[128];
static __device__                int           g_dummy;

// ---------------------------------------------------------------------------
// PTX helpers (legal under virtual arch compute_103 — no 'a' features;
// fp8 mma.sync is an sm_89+ cumulative feature)
// ---------------------------------------------------------------------------
__device__ __forceinline__ uint32_t smem_u32(const void* p) {
    uint32_t a;
    asm("{ .reg .u64 t; cvta.to.shared.u64 t, %1; cvt.u32.u64 %0, t; }" : "=r"(a) : "l"(p));
    return a;
}
__device__ __forceinline__ void cp_async16(uint32_t dst, const void* src) {
    asm volatile("cp.async.cg.shared.global [%0], [%1], 16;" :: "r"(dst), "l"(src) : "memory");
}
__device__ __forceinline__ void cp_commit() { asm volatile("cp.async.commit_group;" ::: "memory"); }
template <int N> __device__ __forceinline__ void cp_wait() {
    asm volatile("cp.async.wait_group %0;" :: "n"(N) : "memory");
}
__device__ __forceinline__ void ldsm_x4(uint32_t& r0, uint32_t& r1, uint32_t& r2, uint32_t& r3,
                                        uint32_t addr) {
    asm volatile("ldmatrix.sync.aligned.m8n8.x4.shared.b16 {%0,%1,%2,%3}, [%4];"
                 : "=r"(r0), "=r"(r1), "=r"(r2), "=r"(r3) : "r"(addr));
}
// FP8 e4m3 MMA, m16n8k32, fp32 accumulate.
__device__ __forceinline__ void mma16832(float* c, const uint32_t* a, const uint32_t* b) {
    asm volatile(
        "mma.sync.aligned.m16n8k32.row.col.f32.e4m3.e4m3.f32 "
        "{%0,%1,%2,%3}, {%4,%5,%6,%7}, {%8,%9}, {%0,%1,%2,%3};\n"
        : "+f"(c[0]), "+f"(c[1]), "+f"(c[2]), "+f"(c[3])
        : "r"(a[0]), "r"(a[1]), "r"(a[2]), "r"(a[3]), "r"(b[0]), "r"(b[1]));
}
__device__ __forceinline__ float fexp_t(float v) {   // acc already sim*log2e/T
    float r;
    asm("ex2.approx.f32 %0, %1;" : "=f"(r) : "f"(v));
    return r;
}
// pack two floats into e4m3x2 (hi, lo)
__device__ __forceinline__ uint16_t cvt_e4m3x2(float hi, float lo) {
    uint16_t r;
    asm("cvt.rn.satfinite.e4m3x2.f32 %0, %1, %2;" : "=h"(r) : "f"(hi), "f"(lo));
    return r;
}

// Job <-> CTA mapping (deterministic, computed on both sides)
__device__ __forceinline__ int job_start(int c) { return c * 28 + (c < 16 ? c : 16); }
__device__ __forceinline__ int job2cta(int j)   { return (j < 464) ? (j / 29) : (16 + (j - 464) / 28); }

// ---------------------------------------------------------------------------
// K1: L2-normalize rows, emit fp8 e4m3. One warp per row; lane l handles
// elements [l*8, l*8+8).
// ---------------------------------------------------------------------------
__global__ void __launch_bounds__(256) k1_normalize(const float* __restrict__ sec,
                                                    const float* __restrict__ ques,
                                                    const float* __restrict__ sent) {
    int wid = (blockIdx.x * blockDim.x + threadIdx.x) >> 5;
    int l = threadIdx.x & 31;
    if (wid >= 16512) return;

    const float* src;
    if (wid < 8192)        src = ques + (size_t)wid * DD;
    else if (wid < 16384)  src = sent + (size_t)(wid - 8192) * DD;
    else                   src = sec  + (size_t)(wid - 16384) * DD;

    float4 v0 = reinterpret_cast<const float4*>(src)[l * 2];
    float4 v1 = reinterpret_cast<const float4*>(src)[l * 2 + 1];
    float x[8] = {v0.x, v0.y, v0.z, v0.w, v1.x, v1.y, v1.z, v1.w};
    float ss = 0.f;
#pragma unroll
    for (int j = 0; j < 8; j++) ss = fmaf(x[j], x[j], ss);
#pragma unroll
    for (int o = 16; o; o >>= 1) ss += __shfl_xor_sync(0xffffffffu, ss, o);
    float scale = 1.0f / fmaxf(sqrtf(ss), 1e-12f);

    unsigned char* dst;
    if (wid < 8192)       { dst = g_qn + (size_t)wid * DD; scale *= QSCALE; }
    else if (wid < 16384) dst = g_sn   + (size_t)(wid - 8192) * DD;
    else                  dst = g_stnb + (size_t)(wid - 16384) * DD;

    uint16_t p0 = cvt_e4m3x2(x[1] * scale, x[0] * scale);
    uint16_t p1 = cvt_e4m3x2(x[3] * scale, x[2] * scale);
    uint16_t p2 = cvt_e4m3x2(x[5] * scale, x[4] * scale);
    uint16_t p3 = cvt_e4m3x2(x[7] * scale, x[6] * scale);
    uint64_t pk = (uint64_t)p0 | ((uint64_t)p1 << 16) | ((uint64_t)p2 << 32) | ((uint64_t)p3 << 48);
    *reinterpret_cast<uint64_t*>(dst + l * 8) = pk;
}

// Dummy kernels: keep ncu's captured launch index on k2 (4th launch).
__global__ void kd1() { if (threadIdx.x == 0) g_dummy = 1; }
__global__ void kd2() { if (threadIdx.x == 0) g_dummy = 2; }

// ---------------------------------------------------------------------------
// K2: flat-balanced fused pass (qs + sq GEMMs), FP8 e4m3 mma.sync.m16n8k32 +
// ldmatrix (16-byte k-chunks) + double-buffered cp.async. 16 warps, 4(M)x4(N),
// warp tile 32x32, 8 ksteps of k=32 bytes.
// ---------------------------------------------------------------------------
__global__ void __launch_bounds__(K2_THREADS, 1) k2_fused() {
    extern __shared__ __align__(1024) char smem[];
    const uint32_t smem_base = smem_u32(smem);

    const int tid = threadIdx.x;
    const int wid = tid >> 5;
    const int lane = tid & 31;
    const int qg = lane >> 2;
    const int qt = lane & 3;

    const int c = blockIdx.x;
    const int s = job_start(c);
    const int e = s + 28 + (c < 16 ? 1 : 0);

    const int warp_m = (wid & 3) * 32;    // 0,32,64,96
    const int wn = wid >> 2;              // 0..3
    const int warp_n = wn * 32;           // 0,32,64,96

    // ldmatrix address bases: mat = 8x8-of-b16 tile index within x4.
    // fp8 view: 16-byte k-chunks; mat0/1 = rows 0-7/8-15 @ k-bytes 0-15,
    // mat2/3 = rows @ k-bytes 16-31 -> exactly the fp8 m16n8k32 fragments.
    const int mat = lane >> 3;
    const int mrow = (mat & 1) * 8 + (lane & 7);
    const int mkof = (mat >> 1) * 16;    // byte offset within kstep
    const uint32_t aBase = smem_base + SM_A + (uint32_t)((warp_m + mrow) * LDT + mkof);
    const uint32_t bBase0 = smem_base + SM_B + (uint32_t)((warp_n + mrow) * LDT + mkof);

    // ---- prefetch B for job s into buf[s&1] ----
    {
        int b0 = s >> 6;
        const unsigned char* bs = ((b0 == 64) ? g_qn : g_sn) + (size_t)((s & 63) * 128) * DD;
        const uint32_t dst = smem_base + SM_B + (s & 1) * TILE_SZ;
#pragma unroll
        for (int j = 0; j < 4; ++j) {
            int idx = j * K2_THREADS + tid;       // 2048 16B chunks
            int r = idx >> 4, cc = idx & 15;
            cp_async16(dst + (uint32_t)(r * LDT + cc * 16), bs + (size_t)r * DD + cc * 16);
        }
        cp_commit();
    }

    int cur_b = -1, sec64 = 0, row0 = 0;
    bool modeQ = false;
    float rsum[4] = {0, 0, 0, 0}, nsum[4] = {0, 0, 0, 0};
    float* rsm = reinterpret_cast<float*>(smem);   // reuses sA region (guarded by syncs)

    for (int j = s; j < e; ++j) {
        const int b = j >> 6;
        if (b != cur_b) {
            if (cur_b >= 0) {
                // ---- finalize previous segment ----
                const int slot = c - job2cta(cur_b << 6);
#pragma unroll
                for (int k = 0; k < 4; ++k) {
                    float v = rsum[k];
                    v += __shfl_xor_sync(0xffffffffu, v, 1);
                    v += __shfl_xor_sync(0xffffffffu, v, 2);
                    if (qt == 0) {
                        int rloc = warp_m + (k >> 1) * 16 + (k & 1) * 8 + qg;
                        rsm[rloc * 4 + wn] = v;
                    }
                }
                __syncthreads();
                if (tid < 128)
                    g_totalP[cur_b][slot][tid] = (rsm[tid * 4] + rsm[tid * 4 + 1]) +
                                                 (rsm[tid * 4 + 2] + rsm[tid * 4 + 3]);
                if (modeQ) {
                    __syncthreads();
#pragma unroll
                    for (int k = 0; k < 4; ++k) {
                        float v = nsum[k];
                        v += __shfl_xor_sync(0xffffffffu, v, 1);
                        v += __shfl_xor_sync(0xffffffffu, v, 2);
                        if (qt == 0) {
                            int rloc = warp_m + (k >> 1) * 16 + (k & 1) * 8 + qg;
                            rsm[rloc * 4 + wn] = v;
                        }
                    }
                    __syncthreads();
                    if (tid < 128)
                        g_sqnumP[slot][tid] = (rsm[tid * 4] + rsm[tid * 4 + 1]) +
                                              (rsm[tid * 4 + 2] + rsm[tid * 4 + 3]);
                }
                __syncthreads();   // rsm reads done before A overwrite
#pragma unroll
                for (int k = 0; k < 4; ++k) { rsum[k] = 0.f; nsum[k] = 0.f; }
            }
            cur_b = b;
            modeQ = (b == 64);
            row0 = modeQ ? 0 : b * 128;
            sec64 = ((row0 + warp_m) >> 6) << 6;
            // ---- load A tile (128 x 256 fp8) ----
            const unsigned char* Asrc = modeQ ? g_stnb : (g_qn + (size_t)row0 * DD);
#pragma unroll
            for (int i = tid; i < 2048; i += K2_THREADS) {
                int r = i >> 4, cc = i & 15;
                *reinterpret_cast<uint4*>(smem + SM_A + r * LDT + cc * 16) =
                    *reinterpret_cast<const uint4*>(Asrc + (size_t)r * DD + cc * 16);
            }
        }

        // ---- prefetch next job's B ----
        if (j + 1 < e) {
            const int jn = j + 1, bn = jn >> 6;
            const unsigned char* bs = ((bn == 64) ? g_qn : g_sn) + (size_t)((jn & 63) * 128) * DD;
            const uint32_t dst = smem_base + SM_B + (jn & 1) * TILE_SZ;
#pragma unroll
            for (int jj = 0; jj < 4; ++jj) {
                int idx = jj * K2_THREADS + tid;
                int r = idx >> 4, cc = idx & 15;
                cp_async16(dst + (uint32_t)(r * LDT + cc * 16), bs + (size_t)r * DD + cc * 16);
            }
            cp_commit();
            cp_wait<1>();
        } else {
            cp_wait<0>();
        }
        __syncthreads();   // buf[j&1] + (possibly) fresh A visible

        const uint32_t bBase = bBase0 + (j & 1) * TILE_SZ;

        float acc[2][4][4];
#pragma unroll
        for (int mt = 0; mt < 2; mt++)
#pragma unroll
            for (int nt = 0; nt < 4; nt++)
#pragma unroll
                for (int z = 0; z < 4; z++) acc[mt][nt][z] = 0.f;

#pragma unroll
        for (int ks = 0; ks < 8; ++ks) {        // 8 ksteps of 32 fp8 bytes
            const uint32_t kb = ks * 32;
            uint32_t a[2][4], bb[4][2];
            ldsm_x4(a[0][0], a[0][1], a[0][2], a[0][3], aBase + kb);
            ldsm_x4(a[1][0], a[1][1], a[1][2], a[1][3], aBase + 16 * LDT + kb);
            ldsm_x4(bb[0][0], bb[1][0], bb[0][1], bb[1][1], bBase + kb);
            ldsm_x4(bb[2][0], bb[3][0], bb[2][1], bb[3][1], bBase + 16 * LDT + kb);
#pragma unroll
            for (int mt = 0; mt < 2; mt++)
#pragma unroll
                for (int nt = 0; nt < 4; nt++)
                    mma16832(acc[mt][nt], a[mt], bb[nt]);
        }

        // ---- epilogue (registers + global stores only), before release bar.
        const int cbw = (j & 63) * 128 + warp_n;     // this warp's 32-col base
        const bool dgQS = !modeQ && ((cbw & ~63) == sec64);
        const int poff = cbw - sec64;                // 0 or 32 when dgQS
#pragma unroll
        for (int mt = 0; mt < 2; mt++) {
#pragma unroll
            for (int h = 0; h < 2; h++) {
                const int rloc = warp_m + mt * 16 + h * 8 + qg;
                float rs0 = 0.f, rs1 = 0.f;
                if (dgQS) {
                    float* pp = g_pos + (size_t)(row0 + rloc) * PP + poff + qt * 2;
#pragma unroll
                    for (int nt = 0; nt < 4; nt++) {
                        float e0 = fexp_t(acc[mt][nt][h * 2 + 0]);
                        float e1 = fexp_t(acc[mt][nt][h * 2 + 1]);
                        rs0 += e0; rs1 += e1;
                        pp[nt * 8 + 0] = e0;
                        pp[nt * 8 + 1] = e1;
                    }
                } else {
#pragma unroll
                    for (int nt = 0; nt < 4; nt++) {
                        rs0 += fexp_t(acc[mt][nt][h * 2 + 0]);
                        rs1 += fexp_t(acc[mt][nt][h * 2 + 1]);
                    }
                }
                float rs = rs0 + rs1;
                rsum[mt * 2 + h] += rs;
                if (modeQ && (rloc == (cbw >> 6))) nsum[mt * 2 + h] += rs;
            }
        }
        __syncthreads();   // all warps done with buf[j&1] (and A for this job)
    }

    // ---- finalize last segment ----
    {
        const int slot = c - job2cta(cur_b << 6);
#pragma unroll
        for (int k = 0; k < 4; ++k) {
            float v = rsum[k];
            v += __shfl_xor_sync(0xffffffffu, v, 1);
            v += __shfl_xor_sync(0xffffffffu, v, 2);
            if (qt == 0) {
                int rloc = warp_m + (k >> 1) * 16 + (k & 1) * 8 + qg;
                rsm[rloc * 4 + wn] = v;
            }
        }
        __syncthreads();
        if (tid < 128)
            g_totalP[cur_b][slot][tid] = (rsm[tid * 4] + rsm[tid * 4 + 1]) +
                                         (rsm[tid * 4 + 2] + rsm[tid * 4 + 3]);
        if (modeQ) {
            __syncthreads();
#pragma unroll
            for (int k = 0; k < 4; ++k) {
                float v = nsum[k];
                v += __shfl_xor_sync(0xffffffffu, v, 1);
                v += __shfl_xor_sync(0xffffffffu, v, 2);
                if (qt == 0) {
                    int rloc = warp_m + (k >> 1) * 16 + (k & 1) * 8 + qg;
                    rsm[rloc * 4 + wn] = v;
                }
            }
            __syncthreads();
            if (tid < 128)
                g_sqnumP[slot][tid] = (rsm[tid * 4] + rsm[tid * 4 + 1]) +
                                      (rsm[tid * 4 + 2] + rsm[tid * 4 + 3]);
        }
    }
}

// ---------------------------------------------------------------------------
// K3: qs loss. One warp handles 8 rows; double accumulation, deterministic.
// ---------------------------------------------------------------------------
__global__ void __launch_bounds__(256) k3_qs_loss() {
    __shared__ double wsum[8];
    const int l = threadIdx.x & 31;
    const int wid = threadIdx.x >> 5;
    const int warpGlobal = blockIdx.x * 8 + wid;

    const float invL = 1.0f / 0.9f;                       // 1/(1-LAM)
    const float term2 = expf(-1.0f / 0.07f) * 8191.0f;    // exp(-1/T)*(N_e-1)

    double acc = 0.0;
    for (int rr = 0; rr < 8; rr++) {
        int row = warpGlobal * 8 + rr;
        float p0 = g_pos[(size_t)row * PP + l];
        float p1 = g_pos[(size_t)row * PP + 32 + l];
        float own = p0 + p1;
#pragma unroll
        for (int o = 16; o; o >>= 1) own += __shfl_xor_sync(0xffffffffu, own, o);
        int b = row >> 7, rl = row & 127;
        float total = (g_totalP[b][0][rl] + g_totalP[b][1][rl]) +
                      (g_totalP[b][2][rl] + g_totalP[b][3][rl]);
        float c1 = (total - own) * invL;

        float t1 = fmaf(-0.1f, p0, c1);
        float Ng0 = fmaxf(fmaxf(t1, term2), 1e-8f);
        float t2 = fmaf(-0.1f, p1, c1);
        float Ng1 = fmaxf(fmaxf(t2, term2), 1e-8f);
        acc += (double)log1pf(Ng0 / p0) + (double)log1pf(Ng1 / p1);
    }
#pragma unroll
    for (int o = 16; o; o >>= 1) acc += __shfl_xor_sync(0xffffffffu, acc, o);
    if (l == 0) wsum[wid] = acc;
    __syncthreads();
    if (threadIdx.x == 0) {
        double ss = 0.0;
        for (int i = 0; i < 8; i++) ss += wsum[i];
        g_qs_part[blockIdx.x] = ss;
    }
}

// ---------------------------------------------------------------------------
// K5: final scalar via parallel tree reduction (deterministic).
// ---------------------------------------------------------------------------
__global__ void __launch_bounds__(128) k5_final(float* __restrict__ out, int out_size) {
    __shared__ double red[128];
    const int t = threadIdx.x;

    float den = (g_totalP[64][0][t] + g_totalP[64][1][t]) +
                (g_totalP[64][2][t] + g_totalP[64][3][t]);
    float num = (g_sqnumP[0][t] + g_sqnumP[1][t]) + (g_sqnumP[2][t] + g_sqnumP[3][t]);
    red[t] = g_qs_part[t] + (log((double)den) - log((double)num));
    __syncthreads();
#pragma unroll
    for (int o = 64; o; o >>= 1) {
        if (t < o) red[t] += red[t + o];
        __syncthreads();
    }
    if (t == 0) {
        float v = (float)red[0];
        for (int i = 0; i < out_size; i++) out[i] = v;
    }
}

// ---------------------------------------------------------------------------
extern "C" void kernel_launch(void* const* d_in, const int* in_sizes, int n_in,
                              void* d_out, int out_size) {
    (void)in_sizes; (void)n_in;
    const float* sec  = (const float*)d_in[1];
    const float* ques = (const float*)d_in[2];
    const float* sent = (const float*)d_in[3];
    float* out = (float*)d_out;

    cudaFuncSetAttribute(k2_fused, cudaFuncAttributeMaxDynamicSharedMemorySize, K2_SMEM);

    k1_normalize<<<2064, 256>>>(sec, ques, sent);
    kd1<<<1, 32>>>();           // keep ncu capture window on k2
    kd2<<<1, 32>>>();
    k2_fused<<<NCTA, K2_THREADS, K2_SMEM>>>();
    k3_qs_loss<<<128, 256>>>();
    k5_final<<<1, 128>>>(out, out_size);
}